// round 1
// baseline (speedup 1.0000x reference)
#include <cuda_runtime.h>
#include <cstdio>

#define D   128
#define H   8
#define DH  16
#define DF  512
#define NQ_MAX  20000
#define NKV_MAX 20000
#define E_MAX   640000

// ---------------- scratch (device globals; no allocations allowed) ----------
__device__ float    g_q[NQ_MAX * D];
__device__ float    g_k[NKV_MAX * D];
__device__ float    g_v[NKV_MAX * D];
__device__ float    g_score[E_MAX * H];
__device__ unsigned g_mx[NQ_MAX * H];
__device__ float    g_den[NQ_MAX * H];
__device__ float    g_attn[NQ_MAX * D];
__device__ float    g_sa[NQ_MAX * D];
__device__ float    g_feat[NQ_MAX * D];
__device__ float    g_hidden[NQ_MAX * DF];
__device__ float    g_ff[NQ_MAX * D];
__device__ float    g_WqT[D * D];
__device__ float    g_WkT[D * D];
__device__ float    g_WvT[D * D];
__device__ float    g_WoT[D * D];
__device__ float    g_W1T[D * DF];   // [K=128][C=512]
__device__ float    g_W2T[DF * D];   // [K=512][C=128]

// ---------------- helpers ----------------------------------------------------
__device__ __forceinline__ unsigned fenc(float f) {
    unsigned u = __float_as_uint(f);
    return (u & 0x80000000u) ? ~u : (u | 0x80000000u);
}
__device__ __forceinline__ float fdec(unsigned u) {
    u = (u & 0x80000000u) ? (u ^ 0x80000000u) : ~u;
    return __uint_as_float(u);
}

// ---------------- weight transpose: W[C][K] -> WT[K][C] ----------------------
__global__ void transpose_kernel(const float* __restrict__ W, float* __restrict__ WT,
                                 int C, int K) {
    int i = blockIdx.x * blockDim.x + threadIdx.x;
    if (i < C * K) {
        int c = i / K, k = i % K;
        WT[k * C + c] = W[i];
    }
}

// ---------------- GEMM: out[N][C] = X[N][KT] @ WT[KT][C] (+bias, +relu) ------
// BM=64 rows/block, BN=128 cols (blockIdx.y selects 128-col tile), 256 threads,
// each thread computes an 8x4 register tile. X staged transposed in smem
// (broadcast reads), WT read as float4 from global (L1-resident).
template <int KT, bool BIAS, bool RELU>
__global__ __launch_bounds__(256)
void gemm_wt(const float* __restrict__ X, const float* __restrict__ WT,
             const float* __restrict__ bias, float* __restrict__ out,
             int N, int C) {
    __shared__ float Xs[128 * 68];

    const int row0 = blockIdx.x * 64;
    const int c0   = blockIdx.y * 128;
    const int tid  = threadIdx.x;
    const int tr   = tid >> 5;        // 0..7  -> row group (8 rows)
    const int tc   = tid & 31;        // 0..31 -> col group (4 cols)

    float acc[8][4];
#pragma unroll
    for (int i = 0; i < 8; i++)
#pragma unroll
        for (int j = 0; j < 4; j++) acc[i][j] = 0.f;

    for (int kc = 0; kc < KT; kc += 128) {
        // stage X tile transposed: Xs[d][r]
#pragma unroll
        for (int it = 0; it < 8; it++) {
            int lin = tid + it * 256;
            int r   = lin >> 5;
            int d4  = lin & 31;
            int row = row0 + r;
            float4 xv = make_float4(0.f, 0.f, 0.f, 0.f);
            if (row < N)
                xv = *(const float4*)(X + (size_t)row * KT + kc + d4 * 4);
            Xs[(d4 * 4 + 0) * 68 + r] = xv.x;
            Xs[(d4 * 4 + 1) * 68 + r] = xv.y;
            Xs[(d4 * 4 + 2) * 68 + r] = xv.z;
            Xs[(d4 * 4 + 3) * 68 + r] = xv.w;
        }
        __syncthreads();

        const float* wp = WT + (size_t)kc * C + c0 + tc * 4;
#pragma unroll 4
        for (int d = 0; d < 128; d++) {
            float4 w  = *(const float4*)(wp + (size_t)d * C);
            float4 xa = *(const float4*)(&Xs[d * 68 + tr * 8]);
            float4 xb = *(const float4*)(&Xs[d * 68 + tr * 8 + 4]);
            float xs[8] = {xa.x, xa.y, xa.z, xa.w, xb.x, xb.y, xb.z, xb.w};
#pragma unroll
            for (int i = 0; i < 8; i++) {
                acc[i][0] += xs[i] * w.x;
                acc[i][1] += xs[i] * w.y;
                acc[i][2] += xs[i] * w.z;
                acc[i][3] += xs[i] * w.w;
            }
        }
        __syncthreads();
    }

    float4 bv = make_float4(0.f, 0.f, 0.f, 0.f);
    if (BIAS) bv = *(const float4*)(bias + c0 + tc * 4);

#pragma unroll
    for (int i = 0; i < 8; i++) {
        int row = row0 + tr * 8 + i;
        if (row < N) {
            float4 o;
            o.x = acc[i][0] + bv.x;
            o.y = acc[i][1] + bv.y;
            o.z = acc[i][2] + bv.z;
            o.w = acc[i][3] + bv.w;
            if (RELU) {
                o.x = fmaxf(o.x, 0.f); o.y = fmaxf(o.y, 0.f);
                o.z = fmaxf(o.z, 0.f); o.w = fmaxf(o.w, 0.f);
            }
            *(float4*)(out + (size_t)row * C + c0 + tc * 4) = o;
        }
    }
}

// ---------------- edge pass 1: score + segment max ---------------------------
__global__ void edge_score_max(const float* __restrict__ k, const float* __restrict__ q,
                               const int* __restrict__ src, const int* __restrict__ dst,
                               float* __restrict__ score, unsigned* __restrict__ mx,
                               int E) {
    int gid = blockIdx.x * blockDim.x + threadIdx.x;
    if (gid >= E * H) return;
    int e = gid >> 3, h = gid & 7;
    int s = src[e], d = dst[e];
    const float4* kp = (const float4*)(k + (size_t)s * D + h * DH);
    const float4* qp = (const float4*)(q + (size_t)d * D + h * DH);
    float acc = 0.f;
#pragma unroll
    for (int i = 0; i < 4; i++) {
        float4 kv = kp[i];
        float4 qv = qp[i];
        acc += kv.x * qv.x + kv.y * qv.y + kv.z * qv.z + kv.w * qv.w;
    }
    acc *= 0.25f;  // 1/sqrt(DH=16)
    score[gid] = acc;
    atomicMax(&mx[d * H + h], fenc(acc));
}

// ---------------- edge pass 2: exp + segment sum ------------------------------
__global__ void edge_exp_sum(const int* __restrict__ dst,
                             float* __restrict__ score,
                             const unsigned* __restrict__ mx,
                             float* __restrict__ den, int E) {
    int gid = blockIdx.x * blockDim.x + threadIdx.x;
    if (gid >= E * H) return;
    int e = gid >> 3, h = gid & 7;
    int d = dst[e];
    float m  = fdec(mx[d * H + h]);
    float ex = __expf(score[gid] - m);
    score[gid] = ex;
    atomicAdd(&den[d * H + h], ex);
}

// ---------------- edge pass 3: weighted scatter of V --------------------------
__global__ void edge_scatter(const float* __restrict__ v,
                             const int* __restrict__ src, const int* __restrict__ dst,
                             const float* __restrict__ score,
                             const float* __restrict__ den,
                             float* __restrict__ attn, int E) {
    int gid = blockIdx.x * blockDim.x + threadIdx.x;
    if (gid >= E * H) return;
    int e = gid >> 3, h = gid & 7;
    int s = src[e], d = dst[e];
    float a = score[gid] / den[d * H + h];
    const float4* vp = (const float4*)(v + (size_t)s * D + h * DH);
    float* op = attn + (size_t)d * D + h * DH;
#pragma unroll
    for (int i = 0; i < 4; i++) {
        float4 vv = vp[i];
        atomicAdd(op + i * 4 + 0, vv.x * a);
        atomicAdd(op + i * 4 + 1, vv.y * a);
        atomicAdd(op + i * 4 + 2, vv.z * a);
        atomicAdd(op + i * 4 + 3, vv.w * a);
    }
}

// ---------------- residual add + layernorm (one row / block of 128) ----------
__global__ void add_ln_kernel(const float* __restrict__ a, const float* __restrict__ b,
                              const float* __restrict__ gamma, const float* __restrict__ beta,
                              float* __restrict__ out) {
    int row = blockIdx.x;
    int t   = threadIdx.x;
    float x = a[(size_t)row * D + t] + b[(size_t)row * D + t];
    float s = x, s2 = x * x;
#pragma unroll
    for (int off = 16; off; off >>= 1) {
        s  += __shfl_xor_sync(0xffffffffu, s,  off);
        s2 += __shfl_xor_sync(0xffffffffu, s2, off);
    }
    __shared__ float ps[4], ps2[4];
    if ((t & 31) == 0) { ps[t >> 5] = s; ps2[t >> 5] = s2; }
    __syncthreads();
    s  = ps[0]  + ps[1]  + ps[2]  + ps[3];
    s2 = ps2[0] + ps2[1] + ps2[2] + ps2[3];
    float mu  = s * (1.f / 128.f);
    float var = s2 * (1.f / 128.f) - mu * mu;
    float inv = rsqrtf(var + 1e-5f);
    out[(size_t)row * D + t] = (x - mu) * inv * gamma[t] + beta[t];
}

// ---------------- launch -----------------------------------------------------
extern "C" void kernel_launch(void* const* d_in, const int* in_sizes, int n_in,
                              void* d_out, int out_size) {
    const float* q_feat  = (const float*)d_in[0];
    const float* kv_feat = (const float*)d_in[1];
    const int*   src     = (const int*)d_in[2];
    const int*   dst     = (const int*)d_in[3];
    const float* Wq      = (const float*)d_in[4];
    const float* Wk      = (const float*)d_in[5];
    const float* Wv      = (const float*)d_in[6];
    const float* Wo      = (const float*)d_in[7];
    const float* W1      = (const float*)d_in[8];
    const float* bf1     = (const float*)d_in[9];
    const float* W2      = (const float*)d_in[10];
    const float* bf2     = (const float*)d_in[11];
    const float* ln1_g   = (const float*)d_in[12];
    const float* ln1_b   = (const float*)d_in[13];
    const float* ln2_g   = (const float*)d_in[14];
    const float* ln2_b   = (const float*)d_in[15];

    const int NQ  = in_sizes[0] / D;
    const int NKV = in_sizes[1] / D;
    const int E   = in_sizes[2];

    float *qp, *kp, *vp, *scp, *denp, *attnp, *sap, *featp, *hidp, *ffp;
    float *wqt, *wkt, *wvt, *wot, *w1t, *w2t;
    unsigned* mxp;
    cudaGetSymbolAddress((void**)&qp,    g_q);
    cudaGetSymbolAddress((void**)&kp,    g_k);
    cudaGetSymbolAddress((void**)&vp,    g_v);
    cudaGetSymbolAddress((void**)&scp,   g_score);
    cudaGetSymbolAddress((void**)&mxp,   g_mx);
    cudaGetSymbolAddress((void**)&denp,  g_den);
    cudaGetSymbolAddress((void**)&attnp, g_attn);
    cudaGetSymbolAddress((void**)&sap,   g_sa);
    cudaGetSymbolAddress((void**)&featp, g_feat);
    cudaGetSymbolAddress((void**)&hidp,  g_hidden);
    cudaGetSymbolAddress((void**)&ffp,   g_ff);
    cudaGetSymbolAddress((void**)&wqt,   g_WqT);
    cudaGetSymbolAddress((void**)&wkt,   g_WkT);
    cudaGetSymbolAddress((void**)&wvt,   g_WvT);
    cudaGetSymbolAddress((void**)&wot,   g_WoT);
    cudaGetSymbolAddress((void**)&w1t,   g_W1T);
    cudaGetSymbolAddress((void**)&w2t,   g_W2T);

    // weight transposes (tiny)
    transpose_kernel<<<(D * D + 255) / 256, 256>>>(Wq, wqt, D, D);
    transpose_kernel<<<(D * D + 255) / 256, 256>>>(Wk, wkt, D, D);
    transpose_kernel<<<(D * D + 255) / 256, 256>>>(Wv, wvt, D, D);
    transpose_kernel<<<(D * D + 255) / 256, 256>>>(Wo, wot, D, D);
    transpose_kernel<<<(DF * D + 255) / 256, 256>>>(W1, w1t, DF, D);   // C=DF, K=D
    transpose_kernel<<<(D * DF + 255) / 256, 256>>>(W2, w2t, D, DF);   // C=D,  K=DF

    // init accumulators (0 encodes below any float for fenc-max)
    cudaMemsetAsync(mxp,   0, (size_t)NQ * H * sizeof(unsigned));
    cudaMemsetAsync(denp,  0, (size_t)NQ * H * sizeof(float));
    cudaMemsetAsync(attnp, 0, (size_t)NQ * D * sizeof(float));

    dim3 gq((NQ + 63) / 64, 1);
    dim3 gkv((NKV + 63) / 64, 1);

    // projections
    gemm_wt<128, false, false><<<gq, 256>>>(q_feat, wqt, nullptr, qp, NQ, D);
    gemm_wt<128, false, false><<<gkv, 256>>>(kv_feat, wkt, nullptr, kp, NKV, D);
    gemm_wt<128, false, false><<<gkv, 256>>>(kv_feat, wvt, nullptr, vp, NKV, D);

    // edge softmax attention
    int eThreads = E * H;
    int eBlocks  = (eThreads + 255) / 256;
    edge_score_max<<<eBlocks, 256>>>(kp, qp, src, dst, scp, mxp, E);
    edge_exp_sum <<<eBlocks, 256>>>(dst, scp, mxp, denp, E);
    edge_scatter <<<eBlocks, 256>>>(vp, src, dst, scp, denp, attnp, E);

    // output projection + residual LN
    gemm_wt<128, false, false><<<gq, 256>>>(attnp, wot, nullptr, sap, NQ, D);
    add_ln_kernel<<<NQ, 128>>>(q_feat, sap, ln1_g, ln1_b, featp);

    // FFN
    dim3 gh((NQ + 63) / 64, DF / 128);
    gemm_wt<128, true, true ><<<gh, 256>>>(featp, w1t, bf1, hidp, NQ, DF);
    gemm_wt<512, true, false><<<gq, 256>>>(hidp, w2t, bf2, ffp, NQ, D);

    // final residual LN -> output
    add_ln_kernel<<<NQ, 128>>>(featp, ffp, ln2_g, ln2_b, (float*)d_out);
}

// round 2
// speedup vs baseline: 1.6374x; 1.6374x over previous
#include <cuda_runtime.h>
#include <cstdio>

#define D   128
#define H   8
#define DH  16
#define DF  512
#define NQ_MAX  20000
#define NKV_MAX 20000
#define E_MAX   640000

// ---------------- scratch (device globals; no allocations allowed) ----------
__device__ float    g_q[NQ_MAX * D];
__device__ float    g_k[NKV_MAX * D];
__device__ float    g_v[NKV_MAX * D];
__device__ float    g_attn[NQ_MAX * D];
__device__ float    g_sa[NQ_MAX * D];
__device__ float    g_feat[NQ_MAX * D];
__device__ float    g_hidden[NQ_MAX * DF];
__device__ float    g_ff[NQ_MAX * D];
__device__ float    g_WqT[D * D];
__device__ float    g_WkT[D * D];
__device__ float    g_WvT[D * D];
__device__ float    g_WoT[D * D];
__device__ float    g_W1T[D * DF];   // [K=128][C=512]
__device__ float    g_W2T[DF * D];   // [K=512][C=128]
// CSR scratch
__device__ int      g_cnt[NQ_MAX];
__device__ int      g_off[NQ_MAX + 1];
__device__ int      g_cursor[NQ_MAX];
__device__ int      g_elist[E_MAX];

// ---------------- weight transpose: W[C][K] -> WT[K][C] ----------------------
__global__ void transpose_kernel(const float* __restrict__ W, float* __restrict__ WT,
                                 int C, int K) {
    int i = blockIdx.x * blockDim.x + threadIdx.x;
    if (i < C * K) {
        int c = i / K, k = i % K;
        WT[k * C + c] = W[i];
    }
}

// ---------------- GEMM: out[N][C] = X[N][KT] @ WT[KT][C] (+bias, +relu) ------
template <int KT, bool BIAS, bool RELU>
__global__ __launch_bounds__(256)
void gemm_wt(const float* __restrict__ X, const float* __restrict__ WT,
             const float* __restrict__ bias, float* __restrict__ out,
             int N, int C) {
    __shared__ float Xs[128 * 68];

    const int row0 = blockIdx.x * 64;
    const int c0   = blockIdx.y * 128;
    const int tid  = threadIdx.x;
    const int tr   = tid >> 5;        // 0..7  -> row group (8 rows)
    const int tc   = tid & 31;        // 0..31 -> col group (4 cols)

    float acc[8][4];
#pragma unroll
    for (int i = 0; i < 8; i++)
#pragma unroll
        for (int j = 0; j < 4; j++) acc[i][j] = 0.f;

    for (int kc = 0; kc < KT; kc += 128) {
#pragma unroll
        for (int it = 0; it < 8; it++) {
            int lin = tid + it * 256;
            int r   = lin >> 5;
            int d4  = lin & 31;
            int row = row0 + r;
            float4 xv = make_float4(0.f, 0.f, 0.f, 0.f);
            if (row < N)
                xv = *(const float4*)(X + (size_t)row * KT + kc + d4 * 4);
            Xs[(d4 * 4 + 0) * 68 + r] = xv.x;
            Xs[(d4 * 4 + 1) * 68 + r] = xv.y;
            Xs[(d4 * 4 + 2) * 68 + r] = xv.z;
            Xs[(d4 * 4 + 3) * 68 + r] = xv.w;
        }
        __syncthreads();

        const float* wp = WT + (size_t)kc * C + c0 + tc * 4;
#pragma unroll 4
        for (int d = 0; d < 128; d++) {
            float4 w  = *(const float4*)(wp + (size_t)d * C);
            float4 xa = *(const float4*)(&Xs[d * 68 + tr * 8]);
            float4 xb = *(const float4*)(&Xs[d * 68 + tr * 8 + 4]);
            float xs[8] = {xa.x, xa.y, xa.z, xa.w, xb.x, xb.y, xb.z, xb.w};
#pragma unroll
            for (int i = 0; i < 8; i++) {
                acc[i][0] += xs[i] * w.x;
                acc[i][1] += xs[i] * w.y;
                acc[i][2] += xs[i] * w.z;
                acc[i][3] += xs[i] * w.w;
            }
        }
        __syncthreads();
    }

    float4 bv = make_float4(0.f, 0.f, 0.f, 0.f);
    if (BIAS) bv = *(const float4*)(bias + c0 + tc * 4);

#pragma unroll
    for (int i = 0; i < 8; i++) {
        int row = row0 + tr * 8 + i;
        if (row < N) {
            float4 o;
            o.x = acc[i][0] + bv.x;
            o.y = acc[i][1] + bv.y;
            o.z = acc[i][2] + bv.z;
            o.w = acc[i][3] + bv.w;
            if (RELU) {
                o.x = fmaxf(o.x, 0.f); o.y = fmaxf(o.y, 0.f);
                o.z = fmaxf(o.z, 0.f); o.w = fmaxf(o.w, 0.f);
            }
            *(float4*)(out + (size_t)row * C + c0 + tc * 4) = o;
        }
    }
}

// ---------------- CSR build --------------------------------------------------
__global__ void hist_kernel(const int* __restrict__ dst, int* __restrict__ cnt, int E) {
    int e = blockIdx.x * blockDim.x + threadIdx.x;
    if (e < E) atomicAdd(&cnt[dst[e]], 1);
}

// single-block exclusive scan over n (<= NQ_MAX) counts; off[n] = total
__global__ __launch_bounds__(1024)
void scan_kernel(const int* __restrict__ cnt, int* __restrict__ off, int n) {
    __shared__ int warp_sums[32];
    __shared__ int carry_s;
    const int tid  = threadIdx.x;
    const int wid  = tid >> 5;
    const int lane = tid & 31;
    if (tid == 0) carry_s = 0;
    __syncthreads();

    for (int base = 0; base < n; base += 1024) {
        int carry = carry_s;
        int idx = base + tid;
        int v = (idx < n) ? cnt[idx] : 0;
        int x = v;
#pragma unroll
        for (int o = 1; o < 32; o <<= 1) {
            int y = __shfl_up_sync(0xffffffffu, x, o);
            if (lane >= o) x += y;
        }
        if (lane == 31) warp_sums[wid] = x;
        __syncthreads();
        if (tid < 32) {
            int w = warp_sums[tid];
#pragma unroll
            for (int o = 1; o < 32; o <<= 1) {
                int y = __shfl_up_sync(0xffffffffu, w, o);
                if (tid >= o) w += y;
            }
            warp_sums[tid] = w;
        }
        __syncthreads();
        int pre  = (wid > 0) ? warp_sums[wid - 1] : 0;
        int incl = x + pre + carry;
        if (idx < n) off[idx] = incl - v;
        __syncthreads();
        if (tid == 1023) carry_s = incl;
        __syncthreads();
    }
    if (tid == 0) off[n] = carry_s;
}

__global__ void fill_kernel(const int* __restrict__ dst, int* __restrict__ cursor,
                            int* __restrict__ elist, int E) {
    int e = blockIdx.x * blockDim.x + threadIdx.x;
    if (e < E) {
        int p = atomicAdd(&cursor[dst[e]], 1);
        elist[p] = e;
    }
}

// ---------------- fused edge-softmax attention (one warp per dst node) -------
// Lane l holds float4 slice [4l, 4l+4) of the 128-dim row; 4-lane group g owns
// head g. Online softmax over this dst's edge list; one coalesced write at end.
__global__ __launch_bounds__(256)
void attn_gather(const float* __restrict__ k, const float* __restrict__ q,
                 const float* __restrict__ v, const int* __restrict__ src,
                 const int* __restrict__ elist, const int* __restrict__ off,
                 float* __restrict__ out, int NQ) {
    int warp = (blockIdx.x * blockDim.x + threadIdx.x) >> 5;
    int lane = threadIdx.x & 31;
    if (warp >= NQ) return;
    const int d = warp;

    float4 qv = *(const float4*)(q + (size_t)d * D + lane * 4);
    int i0 = off[d], i1 = off[d + 1];

    float m = -1e30f, sden = 0.f;
    float4 acc = make_float4(0.f, 0.f, 0.f, 0.f);

    for (int i = i0; i < i1; i++) {
        int e = elist[i];
        int s = src[e];
        float4 kv = *(const float4*)(k + (size_t)s * D + lane * 4);
        float4 vv = *(const float4*)(v + (size_t)s * D + lane * 4);
        float dot = kv.x * qv.x + kv.y * qv.y + kv.z * qv.z + kv.w * qv.w;
        dot += __shfl_xor_sync(0xffffffffu, dot, 1);
        dot += __shfl_xor_sync(0xffffffffu, dot, 2);
        float x  = dot * 0.25f;                    // 1/sqrt(16)
        float mn = fmaxf(m, x);
        float c  = __expf(m - mn);
        float p  = __expf(x - mn);
        sden = sden * c + p;
        acc.x = acc.x * c + p * vv.x;
        acc.y = acc.y * c + p * vv.y;
        acc.z = acc.z * c + p * vv.z;
        acc.w = acc.w * c + p * vv.w;
        m = mn;
    }

    float inv = (sden > 0.f) ? (1.f / sden) : 0.f;
    float4 o = make_float4(acc.x * inv, acc.y * inv, acc.z * inv, acc.w * inv);
    *(float4*)(out + (size_t)d * D + lane * 4) = o;
}

// ---------------- residual add + layernorm (one row / block of 128) ----------
__global__ void add_ln_kernel(const float* __restrict__ a, const float* __restrict__ b,
                              const float* __restrict__ gamma, const float* __restrict__ beta,
                              float* __restrict__ out) {
    int row = blockIdx.x;
    int t   = threadIdx.x;
    float x = a[(size_t)row * D + t] + b[(size_t)row * D + t];
    float s = x, s2 = x * x;
#pragma unroll
    for (int off = 16; off; off >>= 1) {
        s  += __shfl_xor_sync(0xffffffffu, s,  off);
        s2 += __shfl_xor_sync(0xffffffffu, s2, off);
    }
    __shared__ float ps[4], ps2[4];
    if ((t & 31) == 0) { ps[t >> 5] = s; ps2[t >> 5] = s2; }
    __syncthreads();
    s  = ps[0]  + ps[1]  + ps[2]  + ps[3];
    s2 = ps2[0] + ps2[1] + ps2[2] + ps2[3];
    float mu  = s * (1.f / 128.f);
    float var = s2 * (1.f / 128.f) - mu * mu;
    float inv = rsqrtf(var + 1e-5f);
    out[(size_t)row * D + t] = (x - mu) * inv * gamma[t] + beta[t];
}

// ---------------- launch -----------------------------------------------------
extern "C" void kernel_launch(void* const* d_in, const int* in_sizes, int n_in,
                              void* d_out, int out_size) {
    const float* q_feat  = (const float*)d_in[0];
    const float* kv_feat = (const float*)d_in[1];
    const int*   src     = (const int*)d_in[2];
    const int*   dst     = (const int*)d_in[3];
    const float* Wq      = (const float*)d_in[4];
    const float* Wk      = (const float*)d_in[5];
    const float* Wv      = (const float*)d_in[6];
    const float* Wo      = (const float*)d_in[7];
    const float* W1      = (const float*)d_in[8];
    const float* bf1     = (const float*)d_in[9];
    const float* W2      = (const float*)d_in[10];
    const float* bf2     = (const float*)d_in[11];
    const float* ln1_g   = (const float*)d_in[12];
    const float* ln1_b   = (const float*)d_in[13];
    const float* ln2_g   = (const float*)d_in[14];
    const float* ln2_b   = (const float*)d_in[15];

    const int NQ  = in_sizes[0] / D;
    const int NKV = in_sizes[1] / D;
    const int E   = in_sizes[2];

    float *qp, *kp, *vp, *attnp, *sap, *featp, *hidp, *ffp;
    float *wqt, *wkt, *wvt, *wot, *w1t, *w2t;
    int *cntp, *offp, *curp, *elistp;
    cudaGetSymbolAddress((void**)&qp,    g_q);
    cudaGetSymbolAddress((void**)&kp,    g_k);
    cudaGetSymbolAddress((void**)&vp,    g_v);
    cudaGetSymbolAddress((void**)&attnp, g_attn);
    cudaGetSymbolAddress((void**)&sap,   g_sa);
    cudaGetSymbolAddress((void**)&featp, g_feat);
    cudaGetSymbolAddress((void**)&hidp,  g_hidden);
    cudaGetSymbolAddress((void**)&ffp,   g_ff);
    cudaGetSymbolAddress((void**)&wqt,   g_WqT);
    cudaGetSymbolAddress((void**)&wkt,   g_WkT);
    cudaGetSymbolAddress((void**)&wvt,   g_WvT);
    cudaGetSymbolAddress((void**)&wot,   g_WoT);
    cudaGetSymbolAddress((void**)&w1t,   g_W1T);
    cudaGetSymbolAddress((void**)&w2t,   g_W2T);
    cudaGetSymbolAddress((void**)&cntp,  g_cnt);
    cudaGetSymbolAddress((void**)&offp,  g_off);
    cudaGetSymbolAddress((void**)&curp,  g_cursor);
    cudaGetSymbolAddress((void**)&elistp, g_elist);

    // weight transposes (tiny)
    transpose_kernel<<<(D * D + 255) / 256, 256>>>(Wq, wqt, D, D);
    transpose_kernel<<<(D * D + 255) / 256, 256>>>(Wk, wkt, D, D);
    transpose_kernel<<<(D * D + 255) / 256, 256>>>(Wv, wvt, D, D);
    transpose_kernel<<<(D * D + 255) / 256, 256>>>(Wo, wot, D, D);
    transpose_kernel<<<(DF * D + 255) / 256, 256>>>(W1, w1t, DF, D);
    transpose_kernel<<<(D * DF + 255) / 256, 256>>>(W2, w2t, D, DF);

    // ---- CSR build (dst-grouped edge lists) ----
    cudaMemsetAsync(cntp, 0, (size_t)NQ * sizeof(int));
    int eb = (E + 255) / 256;
    hist_kernel<<<eb, 256>>>(dst, cntp, E);
    scan_kernel<<<1, 1024>>>(cntp, offp, NQ);
    cudaMemcpyAsync(curp, offp, (size_t)NQ * sizeof(int), cudaMemcpyDeviceToDevice);
    fill_kernel<<<eb, 256>>>(dst, curp, elistp, E);

    dim3 gq((NQ + 63) / 64, 1);
    dim3 gkv((NKV + 63) / 64, 1);

    // projections
    gemm_wt<128, false, false><<<gq, 256>>>(q_feat, wqt, nullptr, qp, NQ, D);
    gemm_wt<128, false, false><<<gkv, 256>>>(kv_feat, wkt, nullptr, kp, NKV, D);
    gemm_wt<128, false, false><<<gkv, 256>>>(kv_feat, wvt, nullptr, vp, NKV, D);

    // fused one-pass edge-softmax attention (one warp per dst)
    int awarps  = NQ;
    int ablocks = (awarps * 32 + 255) / 256;
    attn_gather<<<ablocks, 256>>>(kp, qp, vp, src, elistp, offp, attnp, NQ);

    // output projection + residual LN
    gemm_wt<128, false, false><<<gq, 256>>>(attnp, wot, nullptr, sap, NQ, D);
    add_ln_kernel<<<NQ, 128>>>(q_feat, sap, ln1_g, ln1_b, featp);

    // FFN
    dim3 gh((NQ + 63) / 64, DF / 128);
    gemm_wt<128, true, true ><<<gh, 256>>>(featp, w1t, bf1, hidp, NQ, DF);
    gemm_wt<512, true, false><<<gq, 256>>>(hidp, w2t, bf2, ffp, NQ, D);

    // final residual LN -> output
    add_ln_kernel<<<NQ, 128>>>(featp, ffp, ln2_g, ln2_b, (float*)d_out);
}

// round 4
// speedup vs baseline: 2.9639x; 1.8101x over previous
#include <cuda_runtime.h>
#include <cuda_bf16.h>
#include <cstdint>

#define D   128
#define H   8
#define DH  16
#define DF  512
#define NQ_MAX  20000
#define NKV_MAX 20000
#define E_MAX   640000

// ---------------- scratch (device globals; no allocations allowed) ----------
__device__ float g_q[NQ_MAX * D];
__device__ float g_k[NKV_MAX * D];
__device__ float g_v[NKV_MAX * D];
__device__ float g_sa[NQ_MAX * D];
__device__ float g_feat[NQ_MAX * D];
__device__ float g_ff[NQ_MAX * D];

__device__ __align__(128) __nv_bfloat16 g_qf_hi[NQ_MAX * D];
__device__ __align__(128) __nv_bfloat16 g_qf_lo[NQ_MAX * D];
__device__ __align__(128) __nv_bfloat16 g_kvf_hi[NKV_MAX * D];
__device__ __align__(128) __nv_bfloat16 g_kvf_lo[NKV_MAX * D];
__device__ __align__(128) __nv_bfloat16 g_attn_hi[NQ_MAX * D];
__device__ __align__(128) __nv_bfloat16 g_attn_lo[NQ_MAX * D];
__device__ __align__(128) __nv_bfloat16 g_feat_hi[NQ_MAX * D];
__device__ __align__(128) __nv_bfloat16 g_feat_lo[NQ_MAX * D];
__device__ __align__(128) __nv_bfloat16 g_hid_hi[NQ_MAX * DF];
__device__ __align__(128) __nv_bfloat16 g_hid_lo[NQ_MAX * DF];
__device__ __align__(128) __nv_bfloat16 g_Wq_hi[D * D],  g_Wq_lo[D * D];
__device__ __align__(128) __nv_bfloat16 g_Wk_hi[D * D],  g_Wk_lo[D * D];
__device__ __align__(128) __nv_bfloat16 g_Wv_hi[D * D],  g_Wv_lo[D * D];
__device__ __align__(128) __nv_bfloat16 g_Wo_hi[D * D],  g_Wo_lo[D * D];
__device__ __align__(128) __nv_bfloat16 g_W1_hi[DF * D], g_W1_lo[DF * D];
__device__ __align__(128) __nv_bfloat16 g_W2_hi[D * DF], g_W2_lo[D * DF];

// CSR scratch
__device__ int g_cnt[NQ_MAX];
__device__ int g_off[NQ_MAX + 1];
__device__ int g_cursor[NQ_MAX];
__device__ int g_elist[E_MAX];

// ---------------- helpers ------------------------------------------------------
__device__ __forceinline__ void f32_hilo(float x, __nv_bfloat16& h, __nv_bfloat16& l) {
    h = __float2bfloat16(x);
    l = __float2bfloat16(x - __bfloat162float(h));
}

__device__ __forceinline__ void mma16816(float* c, const uint32_t* a, const uint32_t* b) {
    asm volatile(
        "mma.sync.aligned.m16n8k16.row.col.f32.bf16.bf16.f32 "
        "{%0,%1,%2,%3}, {%4,%5,%6,%7}, {%8,%9}, {%0,%1,%2,%3};"
        : "+f"(c[0]), "+f"(c[1]), "+f"(c[2]), "+f"(c[3])
        : "r"(a[0]), "r"(a[1]), "r"(a[2]), "r"(a[3]), "r"(b[0]), "r"(b[1]));
}

// ---------------- fp32 -> bf16 hi/lo conversion ------------------------------
__global__ void conv_hilo(const float* __restrict__ x, __nv_bfloat16* __restrict__ hi,
                          __nv_bfloat16* __restrict__ lo, int n) {
    int i = blockIdx.x * blockDim.x + threadIdx.x;
    if (i < n) {
        __nv_bfloat16 h, l;
        f32_hilo(x[i], h, l);
        hi[i] = h; lo[i] = l;
    }
}

// ---------------- tensor-core GEMM: out[N][C] = X[N][K] @ W[C][K]^T ----------
// bf16x3 split emulation via mma.sync m16n8k16. 128x128 CTA tile, 8 warps
// (2x4 grid of 64x32 warp tiles). K staged in 64-chunks in smem, stride 72
// bf16 (144B) for conflict-free fragment loads.
#define KST   72                                    // smem row stride (bf16)
#define BUFB  (128 * KST * 2)                       // 18432 bytes per buffer
#define SMB_A_HI 0
#define SMB_A_LO (BUFB)
#define SMB_B_HI (2 * BUFB)
#define SMB_B_LO (3 * BUFB)
#define GEMM_SMEM (4 * BUFB)                        // 73728 bytes

template<bool BIAS, bool RELU, bool WF32, bool WHILO>
__global__ void __launch_bounds__(256, 2)
gemm_mma(const __nv_bfloat16* __restrict__ Ahi, const __nv_bfloat16* __restrict__ Alo,
         const __nv_bfloat16* __restrict__ Bhi, const __nv_bfloat16* __restrict__ Blo,
         const float* __restrict__ bias,
         float* __restrict__ outf, __nv_bfloat16* __restrict__ outhi,
         __nv_bfloat16* __restrict__ outlo, int Nrows, int C, int K) {
    extern __shared__ char smem[];
    const int tid  = threadIdx.x;
    const int wid  = tid >> 5;
    const int lane = tid & 31;
    const int wr   = wid >> 2;          // 0..1
    const int wc   = wid & 3;           // 0..3
    const int row0 = blockIdx.x * 128;
    const int c0   = blockIdx.y * 128;
    const int gq   = lane >> 2;         // group id 0..7
    const int tg   = lane & 3;          // thread in group

    float acc[4][4][4];
#pragma unroll
    for (int mi = 0; mi < 4; mi++)
#pragma unroll
        for (int ni = 0; ni < 4; ni++)
#pragma unroll
            for (int t = 0; t < 4; t++) acc[mi][ni][t] = 0.f;

    const int NC = K >> 6;
    for (int ch = 0; ch < NC; ch++) {
        const int kc = ch << 6;
        __syncthreads();
        // stage 4 buffers: 128 rows x 64 bf16 each (uint4 = 8 bf16)
#pragma unroll
        for (int i = 0; i < 16; i++) {
            int id  = tid + (i << 8);          // 0..4095
            int buf = id >> 10;
            int rem = id & 1023;
            int r   = rem >> 3;
            int c8  = rem & 7;
            const __nv_bfloat16* g;
            int rg;
            int sbase;
            if (buf == 0)      { g = Ahi; rg = min(row0 + r, Nrows - 1); sbase = SMB_A_HI; }
            else if (buf == 1) { g = Alo; rg = min(row0 + r, Nrows - 1); sbase = SMB_A_LO; }
            else if (buf == 2) { g = Bhi; rg = c0 + r;                   sbase = SMB_B_HI; }
            else               { g = Blo; rg = c0 + r;                   sbase = SMB_B_LO; }
            uint4 v = *(const uint4*)(g + (size_t)rg * K + kc + (c8 << 3));
            *(uint4*)(smem + sbase + r * (KST * 2) + (c8 << 4)) = v;
        }
        __syncthreads();

#pragma unroll
        for (int ks = 0; ks < 4; ks++) {
            const int kb = (ks << 4) + (tg << 1);      // bf16 col within chunk
            // B fragments (hi & lo) for this kstep: 4 n-frags x 2 regs
            uint32_t bh[4][2], bl[4][2];
#pragma unroll
            for (int ni = 0; ni < 4; ni++) {
                int n = wc * 32 + ni * 8 + gq;
                const char* pbh = smem + SMB_B_HI + n * (KST * 2) + kb * 2;
                const char* pbl = smem + SMB_B_LO + n * (KST * 2) + kb * 2;
                bh[ni][0] = *(const uint32_t*)(pbh);
                bh[ni][1] = *(const uint32_t*)(pbh + 16);
                bl[ni][0] = *(const uint32_t*)(pbl);
                bl[ni][1] = *(const uint32_t*)(pbl + 16);
            }
#pragma unroll
            for (int mi = 0; mi < 4; mi++) {
                int r = wr * 64 + mi * 16 + gq;
                const char* pah = smem + SMB_A_HI + r * (KST * 2) + kb * 2;
                const char* pal = smem + SMB_A_LO + r * (KST * 2) + kb * 2;
                uint32_t ah[4], al[4];
                ah[0] = *(const uint32_t*)(pah);
                ah[1] = *(const uint32_t*)(pah + 8 * (KST * 2));
                ah[2] = *(const uint32_t*)(pah + 16);
                ah[3] = *(const uint32_t*)(pah + 8 * (KST * 2) + 16);
                al[0] = *(const uint32_t*)(pal);
                al[1] = *(const uint32_t*)(pal + 8 * (KST * 2));
                al[2] = *(const uint32_t*)(pal + 16);
                al[3] = *(const uint32_t*)(pal + 8 * (KST * 2) + 16);
#pragma unroll
                for (int ni = 0; ni < 4; ni++) {
                    mma16816(acc[mi][ni], ah, bh[ni]);
                    mma16816(acc[mi][ni], ah, bl[ni]);
                    mma16816(acc[mi][ni], al, bh[ni]);
                }
            }
        }
    }

    // epilogue: registers -> gmem
#pragma unroll
    for (int mi = 0; mi < 4; mi++) {
#pragma unroll
        for (int half = 0; half < 2; half++) {
            int r = row0 + wr * 64 + mi * 16 + gq + half * 8;
            if (r >= Nrows) continue;
#pragma unroll
            for (int ni = 0; ni < 4; ni++) {
                int c = c0 + wc * 32 + ni * 8 + tg * 2;
                float v0 = acc[mi][ni][half * 2 + 0];
                float v1 = acc[mi][ni][half * 2 + 1];
                if (BIAS) { v0 += bias[c]; v1 += bias[c + 1]; }
                if (RELU) { v0 = fmaxf(v0, 0.f); v1 = fmaxf(v1, 0.f); }
                size_t o = (size_t)r * C + c;
                if (WF32) *(float2*)(outf + o) = make_float2(v0, v1);
                if (WHILO) {
                    __nv_bfloat16 h0, l0, h1, l1;
                    f32_hilo(v0, h0, l0); f32_hilo(v1, h1, l1);
                    __nv_bfloat162 hh; hh.x = h0; hh.y = h1;
                    __nv_bfloat162 ll; ll.x = l0; ll.y = l1;
                    *(__nv_bfloat162*)(outhi + o) = hh;
                    *(__nv_bfloat162*)(outlo + o) = ll;
                }
            }
        }
    }
}

// ---------------- CSR build --------------------------------------------------
__global__ void hist_kernel(const int* __restrict__ dst, int* __restrict__ cnt, int E) {
    int e = blockIdx.x * blockDim.x + threadIdx.x;
    if (e < E) atomicAdd(&cnt[dst[e]], 1);
}

__global__ __launch_bounds__(1024)
void scan_kernel(const int* __restrict__ cnt, int* __restrict__ off, int n) {
    __shared__ int warp_sums[32];
    __shared__ int carry_s;
    const int tid  = threadIdx.x;
    const int wid  = tid >> 5;
    const int lane = tid & 31;
    if (tid == 0) carry_s = 0;
    __syncthreads();

    for (int base = 0; base < n; base += 1024) {
        int carry = carry_s;
        int idx = base + tid;
        int v = (idx < n) ? cnt[idx] : 0;
        int x = v;
#pragma unroll
        for (int o = 1; o < 32; o <<= 1) {
            int y = __shfl_up_sync(0xffffffffu, x, o);
            if (lane >= o) x += y;
        }
        if (lane == 31) warp_sums[wid] = x;
        __syncthreads();
        if (tid < 32) {
            int w = warp_sums[tid];
#pragma unroll
            for (int o = 1; o < 32; o <<= 1) {
                int y = __shfl_up_sync(0xffffffffu, w, o);
                if (tid >= o) w += y;
            }
            warp_sums[tid] = w;
        }
        __syncthreads();
        int pre  = (wid > 0) ? warp_sums[wid - 1] : 0;
        int incl = x + pre + carry;
        if (idx < n) off[idx] = incl - v;
        __syncthreads();
        if (tid == 1023) carry_s = incl;
        __syncthreads();
    }
    if (tid == 0) off[n] = carry_s;
}

__global__ void fill_kernel(const int* __restrict__ dst, int* __restrict__ cursor,
                            int* __restrict__ elist, int E) {
    int e = blockIdx.x * blockDim.x + threadIdx.x;
    if (e < E) {
        int p = atomicAdd(&cursor[dst[e]], 1);
        elist[p] = e;
    }
}

// ---------------- fused edge-softmax attention (one warp per dst node) -------
__global__ __launch_bounds__(256)
void attn_gather(const float* __restrict__ k, const float* __restrict__ q,
                 const float* __restrict__ v, const int* __restrict__ src,
                 const int* __restrict__ elist, const int* __restrict__ off,
                 __nv_bfloat16* __restrict__ out_hi, __nv_bfloat16* __restrict__ out_lo,
                 int NQ) {
    int warp = (blockIdx.x * blockDim.x + threadIdx.x) >> 5;
    int lane = threadIdx.x & 31;
    if (warp >= NQ) return;
    const int d = warp;

    float4 qv = *(const float4*)(q + (size_t)d * D + lane * 4);
    int i0 = off[d], i1 = off[d + 1];

    float m = -1e30f, sden = 0.f;
    float4 acc = make_float4(0.f, 0.f, 0.f, 0.f);

    for (int i = i0; i < i1; i++) {
        int e = elist[i];
        int s = src[e];
        float4 kv = *(const float4*)(k + (size_t)s * D + lane * 4);
        float4 vv = *(const float4*)(v + (size_t)s * D + lane * 4);
        float dot = kv.x * qv.x + kv.y * qv.y + kv.z * qv.z + kv.w * qv.w;
        dot += __shfl_xor_sync(0xffffffffu, dot, 1);
        dot += __shfl_xor_sync(0xffffffffu, dot, 2);
        float x  = dot * 0.25f;
        float mn = fmaxf(m, x);
        float c  = __expf(m - mn);
        float p  = __expf(x - mn);
        sden = sden * c + p;
        acc.x = acc.x * c + p * vv.x;
        acc.y = acc.y * c + p * vv.y;
        acc.z = acc.z * c + p * vv.z;
        acc.w = acc.w * c + p * vv.w;
        m = mn;
    }

    float inv = (sden > 0.f) ? (1.f / sden) : 0.f;
    float4 o = make_float4(acc.x * inv, acc.y * inv, acc.z * inv, acc.w * inv);
    __nv_bfloat16 h[4], l[4];
    f32_hilo(o.x, h[0], l[0]); f32_hilo(o.y, h[1], l[1]);
    f32_hilo(o.z, h[2], l[2]); f32_hilo(o.w, h[3], l[3]);
    size_t ob = (size_t)d * D + lane * 4;
    *(uint2*)(out_hi + ob) = *(uint2*)h;
    *(uint2*)(out_lo + ob) = *(uint2*)l;
}

// ---------------- residual add + layernorm ------------------------------------
template<bool WHILO>
__global__ void add_ln_kernel(const float* __restrict__ a, const float* __restrict__ b,
                              const float* __restrict__ gamma, const float* __restrict__ beta,
                              float* __restrict__ out,
                              __nv_bfloat16* __restrict__ out_hi,
                              __nv_bfloat16* __restrict__ out_lo) {
    int row = blockIdx.x;
    int t   = threadIdx.x;
    float x = a[(size_t)row * D + t] + b[(size_t)row * D + t];
    float s = x, s2 = x * x;
#pragma unroll
    for (int off = 16; off; off >>= 1) {
        s  += __shfl_xor_sync(0xffffffffu, s,  off);
        s2 += __shfl_xor_sync(0xffffffffu, s2, off);
    }
    __shared__ float ps[4], ps2[4];
    if ((t & 31) == 0) { ps[t >> 5] = s; ps2[t >> 5] = s2; }
    __syncthreads();
    s  = ps[0]  + ps[1]  + ps[2]  + ps[3];
    s2 = ps2[0] + ps2[1] + ps2[2] + ps2[3];
    float mu  = s * (1.f / 128.f);
    float var = s2 * (1.f / 128.f) - mu * mu;
    float invs = rsqrtf(var + 1e-5f);
    float y = (x - mu) * invs * gamma[t] + beta[t];
    out[(size_t)row * D + t] = y;
    if (WHILO) {
        __nv_bfloat16 h, l;
        f32_hilo(y, h, l);
        out_hi[(size_t)row * D + t] = h;
        out_lo[(size_t)row * D + t] = l;
    }
}

// ---------------- launch -----------------------------------------------------
extern "C" void kernel_launch(void* const* d_in, const int* in_sizes, int n_in,
                              void* d_out, int out_size) {
    const float* q_feat  = (const float*)d_in[0];
    const float* kv_feat = (const float*)d_in[1];
    const int*   src     = (const int*)d_in[2];
    const int*   dst     = (const int*)d_in[3];
    const float* Wq      = (const float*)d_in[4];
    const float* Wk      = (const float*)d_in[5];
    const float* Wv      = (const float*)d_in[6];
    const float* Wo      = (const float*)d_in[7];
    const float* W1      = (const float*)d_in[8];
    const float* bf1     = (const float*)d_in[9];
    const float* W2      = (const float*)d_in[10];
    const float* bf2     = (const float*)d_in[11];
    const float* ln1_g   = (const float*)d_in[12];
    const float* ln1_b   = (const float*)d_in[13];
    const float* ln2_g   = (const float*)d_in[14];
    const float* ln2_b   = (const float*)d_in[15];

    const int NQ  = in_sizes[0] / D;
    const int NKV = in_sizes[1] / D;
    const int E   = in_sizes[2];

    float *qp, *kp, *vp, *sap, *featp, *ffp;
    __nv_bfloat16 *qfh, *qfl, *kvfh, *kvfl, *ath, *atl, *fth, *ftl, *hdh, *hdl;
    __nv_bfloat16 *wqh, *wql, *wkh, *wkl, *wvh, *wvl, *woh, *wol, *w1h, *w1l, *w2h, *w2l;
    int *cntp, *offp, *curp, *elistp;
    cudaGetSymbolAddress((void**)&qp,    g_q);
    cudaGetSymbolAddress((void**)&kp,    g_k);
    cudaGetSymbolAddress((void**)&vp,    g_v);
    cudaGetSymbolAddress((void**)&sap,   g_sa);
    cudaGetSymbolAddress((void**)&featp, g_feat);
    cudaGetSymbolAddress((void**)&ffp,   g_ff);
    cudaGetSymbolAddress((void**)&qfh,   g_qf_hi);   cudaGetSymbolAddress((void**)&qfl, g_qf_lo);
    cudaGetSymbolAddress((void**)&kvfh,  g_kvf_hi);  cudaGetSymbolAddress((void**)&kvfl, g_kvf_lo);
    cudaGetSymbolAddress((void**)&ath,   g_attn_hi); cudaGetSymbolAddress((void**)&atl, g_attn_lo);
    cudaGetSymbolAddress((void**)&fth,   g_feat_hi); cudaGetSymbolAddress((void**)&ftl, g_feat_lo);
    cudaGetSymbolAddress((void**)&hdh,   g_hid_hi);  cudaGetSymbolAddress((void**)&hdl, g_hid_lo);
    cudaGetSymbolAddress((void**)&wqh,   g_Wq_hi);   cudaGetSymbolAddress((void**)&wql, g_Wq_lo);
    cudaGetSymbolAddress((void**)&wkh,   g_Wk_hi);   cudaGetSymbolAddress((void**)&wkl, g_Wk_lo);
    cudaGetSymbolAddress((void**)&wvh,   g_Wv_hi);   cudaGetSymbolAddress((void**)&wvl, g_Wv_lo);
    cudaGetSymbolAddress((void**)&woh,   g_Wo_hi);   cudaGetSymbolAddress((void**)&wol, g_Wo_lo);
    cudaGetSymbolAddress((void**)&w1h,   g_W1_hi);   cudaGetSymbolAddress((void**)&w1l, g_W1_lo);
    cudaGetSymbolAddress((void**)&w2h,   g_W2_hi);   cudaGetSymbolAddress((void**)&w2l, g_W2_lo);
    cudaGetSymbolAddress((void**)&cntp,  g_cnt);
    cudaGetSymbolAddress((void**)&offp,  g_off);
    cudaGetSymbolAddress((void**)&curp,  g_cursor);
    cudaGetSymbolAddress((void**)&elistp, g_elist);

    cudaFuncSetAttribute(gemm_mma<false, false, true,  false>,
                         cudaFuncAttributeMaxDynamicSharedMemorySize, GEMM_SMEM);
    cudaFuncSetAttribute(gemm_mma<true,  true,  false, true>,
                         cudaFuncAttributeMaxDynamicSharedMemorySize, GEMM_SMEM);
    cudaFuncSetAttribute(gemm_mma<true,  false, true,  false>,
                         cudaFuncAttributeMaxDynamicSharedMemorySize, GEMM_SMEM);

    // input + weight conversions to bf16 hi/lo
    conv_hilo<<<(NQ * D + 255) / 256, 256>>>(q_feat, qfh, qfl, NQ * D);
    conv_hilo<<<(NKV * D + 255) / 256, 256>>>(kv_feat, kvfh, kvfl, NKV * D);
    conv_hilo<<<(D * D + 255) / 256, 256>>>(Wq, wqh, wql, D * D);
    conv_hilo<<<(D * D + 255) / 256, 256>>>(Wk, wkh, wkl, D * D);
    conv_hilo<<<(D * D + 255) / 256, 256>>>(Wv, wvh, wvl, D * D);
    conv_hilo<<<(D * D + 255) / 256, 256>>>(Wo, woh, wol, D * D);
    conv_hilo<<<(DF * D + 255) / 256, 256>>>(W1, w1h, w1l, DF * D);
    conv_hilo<<<(D * DF + 255) / 256, 256>>>(W2, w2h, w2l, D * DF);

    // CSR build (dst-grouped edge lists)
    cudaMemsetAsync(cntp, 0, (size_t)NQ * sizeof(int));
    int eb = (E + 255) / 256;
    hist_kernel<<<eb, 256>>>(dst, cntp, E);
    scan_kernel<<<1, 1024>>>(cntp, offp, NQ);
    cudaMemcpyAsync(curp, offp, (size_t)NQ * sizeof(int), cudaMemcpyDeviceToDevice);
    fill_kernel<<<eb, 256>>>(dst, curp, elistp, E);

    const int MTq  = (NQ + 127) / 128;
    const int MTkv = (NKV + 127) / 128;

    // projections (tensor core)
    gemm_mma<false, false, true, false><<<dim3(MTq, 1), 256, GEMM_SMEM>>>(
        qfh, qfl, wqh, wql, nullptr, qp, nullptr, nullptr, NQ, D, D);
    gemm_mma<false, false, true, false><<<dim3(MTkv, 1), 256, GEMM_SMEM>>>(
        kvfh, kvfl, wkh, wkl, nullptr, kp, nullptr, nullptr, NKV, D, D);
    gemm_mma<false, false, true, false><<<dim3(MTkv, 1), 256, GEMM_SMEM>>>(
        kvfh, kvfl, wvh, wvl, nullptr, vp, nullptr, nullptr, NKV, D, D);

    // fused one-pass edge-softmax attention (one warp per dst)
    int ablocks = (NQ * 32 + 255) / 256;
    attn_gather<<<ablocks, 256>>>(kp, qp, vp, src, elistp, offp, ath, atl, NQ);

    // output projection + residual LN
    gemm_mma<false, false, true, false><<<dim3(MTq, 1), 256, GEMM_SMEM>>>(
        ath, atl, woh, wol, nullptr, sap, nullptr, nullptr, NQ, D, D);
    add_ln_kernel<true><<<NQ, 128>>>(q_feat, sap, ln1_g, ln1_b, featp, fth, ftl);

    // FFN
    gemm_mma<true, true, false, true><<<dim3(MTq, 4), 256, GEMM_SMEM>>>(
        fth, ftl, w1h, w1l, bf1, nullptr, hdh, hdl, NQ, DF, D);
    gemm_mma<true, false, true, false><<<dim3(MTq, 1), 256, GEMM_SMEM>>>(
        hdh, hdl, w2h, w2l, bf2, ffp, nullptr, nullptr, NQ, D, DF);

    // final residual LN -> output
    add_ln_kernel<false><<<NQ, 128>>>(featp, ffp, ln2_g, ln2_b, (float*)d_out, nullptr, nullptr);
}

// round 5
// speedup vs baseline: 3.2893x; 1.1098x over previous
#include <cuda_runtime.h>
#include <cuda_bf16.h>
#include <cstdint>

#define D   128
#define H   8
#define DH  16
#define DF  512
#define NQ_MAX  20000
#define NKV_MAX 20000
#define E_MAX   640000

// ---------------- scratch (device globals; no allocations allowed) ----------
__device__ float g_q[NQ_MAX * D];
__device__ float g_k[NKV_MAX * D];
__device__ float g_v[NKV_MAX * D];
__device__ float g_sa[NQ_MAX * D];
__device__ float g_feat[NQ_MAX * D];
__device__ float g_ff[NQ_MAX * D];

__device__ __align__(128) __nv_bfloat16 g_qf_hi[NQ_MAX * D];
__device__ __align__(128) __nv_bfloat16 g_qf_lo[NQ_MAX * D];
__device__ __align__(128) __nv_bfloat16 g_kvf_hi[NKV_MAX * D];
__device__ __align__(128) __nv_bfloat16 g_kvf_lo[NKV_MAX * D];
__device__ __align__(128) __nv_bfloat16 g_attn_hi[NQ_MAX * D];
__device__ __align__(128) __nv_bfloat16 g_attn_lo[NQ_MAX * D];
__device__ __align__(128) __nv_bfloat16 g_feat_hi[NQ_MAX * D];
__device__ __align__(128) __nv_bfloat16 g_feat_lo[NQ_MAX * D];
__device__ __align__(128) __nv_bfloat16 g_hid_hi[NQ_MAX * DF];
__device__ __align__(128) __nv_bfloat16 g_hid_lo[NQ_MAX * DF];
__device__ __align__(128) __nv_bfloat16 g_Wq_hi[D * D],  g_Wq_lo[D * D];
__device__ __align__(128) __nv_bfloat16 g_Wk_hi[D * D],  g_Wk_lo[D * D];
__device__ __align__(128) __nv_bfloat16 g_Wv_hi[D * D],  g_Wv_lo[D * D];
__device__ __align__(128) __nv_bfloat16 g_Wo_hi[D * D],  g_Wo_lo[D * D];
__device__ __align__(128) __nv_bfloat16 g_W1_hi[DF * D], g_W1_lo[DF * D];
__device__ __align__(128) __nv_bfloat16 g_W2_hi[D * DF], g_W2_lo[D * DF];

// CSR scratch
__device__ int g_cnt[NQ_MAX];
__device__ int g_off[NQ_MAX + 1];
__device__ int g_cursor[NQ_MAX];
__device__ int g_slist[E_MAX];     // src id per CSR slot (no indirection)

// ---------------- helpers ------------------------------------------------------
__device__ __forceinline__ uint32_t smem_u32(const void* p) {
    uint32_t a;
    asm("{ .reg .u64 t; cvta.to.shared.u64 t, %1; cvt.u32.u64 %0, t; }" : "=r"(a) : "l"(p));
    return a;
}
__device__ __forceinline__ void f32_hilo(float x, __nv_bfloat16& h, __nv_bfloat16& l) {
    h = __float2bfloat16(x);
    l = __float2bfloat16(x - __bfloat162float(h));
}
__device__ __forceinline__ void mma16816(float* c, const uint32_t* a, const uint32_t* b) {
    asm volatile(
        "mma.sync.aligned.m16n8k16.row.col.f32.bf16.bf16.f32 "
        "{%0,%1,%2,%3}, {%4,%5,%6,%7}, {%8,%9}, {%0,%1,%2,%3};"
        : "+f"(c[0]), "+f"(c[1]), "+f"(c[2]), "+f"(c[3])
        : "r"(a[0]), "r"(a[1]), "r"(a[2]), "r"(a[3]), "r"(b[0]), "r"(b[1]));
}

// ---------------- conversions -------------------------------------------------
__global__ void conv_inputs(const float* __restrict__ qf, const float* __restrict__ kvf,
                            __nv_bfloat16* __restrict__ qh, __nv_bfloat16* __restrict__ ql,
                            __nv_bfloat16* __restrict__ kh, __nv_bfloat16* __restrict__ kl,
                            int nq, int ntot) {
    int i = blockIdx.x * blockDim.x + threadIdx.x;
    if (i >= ntot) return;
    __nv_bfloat16 h, l;
    if (i < nq) {
        f32_hilo(qf[i], h, l);
        qh[i] = h; ql[i] = l;
    } else {
        int j = i - nq;
        f32_hilo(kvf[j], h, l);
        kh[j] = h; kl[j] = l;
    }
}

__global__ void conv_weights(const float* __restrict__ Wq, const float* __restrict__ Wk,
                             const float* __restrict__ Wv, const float* __restrict__ Wo,
                             const float* __restrict__ W1, const float* __restrict__ W2,
                             __nv_bfloat16* __restrict__ qh, __nv_bfloat16* __restrict__ ql,
                             __nv_bfloat16* __restrict__ kh, __nv_bfloat16* __restrict__ kl,
                             __nv_bfloat16* __restrict__ vh, __nv_bfloat16* __restrict__ vl,
                             __nv_bfloat16* __restrict__ oh, __nv_bfloat16* __restrict__ ol,
                             __nv_bfloat16* __restrict__ w1h, __nv_bfloat16* __restrict__ w1l,
                             __nv_bfloat16* __restrict__ w2h, __nv_bfloat16* __restrict__ w2l) {
    int i = blockIdx.x * blockDim.x + threadIdx.x;     // 0 .. 196607
    const float* src; __nv_bfloat16 *ho, *lo_; int r;
    if (i < 65536) {
        int which = i >> 14; r = i & 16383;
        if (which == 0)      { src = Wq; ho = qh; lo_ = ql; }
        else if (which == 1) { src = Wk; ho = kh; lo_ = kl; }
        else if (which == 2) { src = Wv; ho = vh; lo_ = vl; }
        else                 { src = Wo; ho = oh; lo_ = ol; }
    } else if (i < 131072) { r = i - 65536;  src = W1; ho = w1h; lo_ = w1l; }
    else                   { r = i - 131072; src = W2; ho = w2h; lo_ = w2l; }
    __nv_bfloat16 h, l;
    f32_hilo(src[r], h, l);
    ho[r] = h; lo_[r] = l;
}

// ---------------- tensor-core GEMM: out[N][C] = X[N][K] @ W[C][K]^T ----------
// bf16x3 split, mma.sync m16n8k16, 128x128 CTA tile, 8 warps (2x4 of 64x32).
// cp.async 2-stage pipeline, K-chunk 32, smem row stride 80B (conflict-free).
#define KSTB  80
#define BUF   (128 * KSTB)                 // 10240 bytes
#define STAGE (4 * BUF)                    // 40960 per stage
#define GEMM_SMEM (2 * STAGE)              // 81920 bytes

__device__ __forceinline__ void stage32(uint32_t sbase, int tid,
    const __nv_bfloat16* __restrict__ Ahi, const __nv_bfloat16* __restrict__ Alo,
    const __nv_bfloat16* __restrict__ Bhi, const __nv_bfloat16* __restrict__ Blo,
    int row0, int c0, int kc, int K, int Nrows) {
#pragma unroll
    for (int j = 0; j < 8; j++) {
        int id  = tid + (j << 8);          // 0..2047
        int buf = id >> 9;
        int rem = id & 511;
        int r   = rem >> 2;
        int c16 = rem & 3;
        const __nv_bfloat16* g;
        int rg;
        if (buf == 0)      { g = Ahi; rg = min(row0 + r, Nrows - 1); }
        else if (buf == 1) { g = Alo; rg = min(row0 + r, Nrows - 1); }
        else if (buf == 2) { g = Bhi; rg = c0 + r; }
        else               { g = Blo; rg = c0 + r; }
        uint32_t daddr = sbase + buf * BUF + r * KSTB + c16 * 16;
        unsigned long long gsrc =
            (unsigned long long)__cvta_generic_to_global(g + (size_t)rg * K + kc + c16 * 8);
        asm volatile("cp.async.cg.shared.global [%0], [%1], 16;"
                     :: "r"(daddr), "l"(gsrc) : "memory");
    }
}

template<bool BIAS, bool RELU, bool WF32, bool WHILO>
__global__ void __launch_bounds__(256, 2)
gemm_mma(const __nv_bfloat16* __restrict__ Ahi, const __nv_bfloat16* __restrict__ Alo,
         const __nv_bfloat16* __restrict__ Bhi, const __nv_bfloat16* __restrict__ Blo,
         const float* __restrict__ bias,
         float* __restrict__ outf, __nv_bfloat16* __restrict__ outhi,
         __nv_bfloat16* __restrict__ outlo, int Nrows, int C, int K) {
    extern __shared__ char smem[];
    const uint32_t sb = smem_u32(smem);
    const int tid  = threadIdx.x;
    const int wid  = tid >> 5;
    const int lane = tid & 31;
    const int wr   = wid >> 2;
    const int wc   = wid & 3;
    const int row0 = blockIdx.x * 128;
    const int c0   = blockIdx.y * 128;
    const int gq   = lane >> 2;
    const int tg   = lane & 3;

    float acc[4][4][4];
#pragma unroll
    for (int mi = 0; mi < 4; mi++)
#pragma unroll
        for (int ni = 0; ni < 4; ni++)
#pragma unroll
            for (int t = 0; t < 4; t++) acc[mi][ni][t] = 0.f;

    const int NC = K >> 5;
    stage32(sb, tid, Ahi, Alo, Bhi, Blo, row0, c0, 0, K, Nrows);
    asm volatile("cp.async.commit_group;" ::: "memory");

    for (int ch = 0; ch < NC; ch++) {
        if (ch + 1 < NC) {
            stage32(sb + ((ch + 1) & 1) * STAGE, tid, Ahi, Alo, Bhi, Blo,
                    row0, c0, (ch + 1) << 5, K, Nrows);
            asm volatile("cp.async.commit_group;" ::: "memory");
            asm volatile("cp.async.wait_group 1;" ::: "memory");
        } else {
            asm volatile("cp.async.wait_group 0;" ::: "memory");
        }
        __syncthreads();

        const char* sAh = smem + (ch & 1) * STAGE;
        const char* sAl = sAh + BUF;
        const char* sBh = sAh + 2 * BUF;
        const char* sBl = sAh + 3 * BUF;

#pragma unroll
        for (int ks = 0; ks < 2; ks++) {
            const int kbyte = (ks << 5) + (tg << 2);
            uint32_t bh[4][2], bl[4][2];
#pragma unroll
            for (int ni = 0; ni < 4; ni++) {
                int n = wc * 32 + ni * 8 + gq;
                const char* pbh = sBh + n * KSTB + kbyte;
                const char* pbl = sBl + n * KSTB + kbyte;
                bh[ni][0] = *(const uint32_t*)(pbh);
                bh[ni][1] = *(const uint32_t*)(pbh + 16);
                bl[ni][0] = *(const uint32_t*)(pbl);
                bl[ni][1] = *(const uint32_t*)(pbl + 16);
            }
#pragma unroll
            for (int mi = 0; mi < 4; mi++) {
                int r = wr * 64 + mi * 16 + gq;
                const char* pah = sAh + r * KSTB + kbyte;
                const char* pal = sAl + r * KSTB + kbyte;
                uint32_t ah[4], al[4];
                ah[0] = *(const uint32_t*)(pah);
                ah[1] = *(const uint32_t*)(pah + 8 * KSTB);
                ah[2] = *(const uint32_t*)(pah + 16);
                ah[3] = *(const uint32_t*)(pah + 8 * KSTB + 16);
                al[0] = *(const uint32_t*)(pal);
                al[1] = *(const uint32_t*)(pal + 8 * KSTB);
                al[2] = *(const uint32_t*)(pal + 16);
                al[3] = *(const uint32_t*)(pal + 8 * KSTB + 16);
#pragma unroll
                for (int ni = 0; ni < 4; ni++) {
                    mma16816(acc[mi][ni], ah, bh[ni]);
                    mma16816(acc[mi][ni], ah, bl[ni]);
                    mma16816(acc[mi][ni], al, bh[ni]);
                }
            }
        }
        __syncthreads();
    }

    // epilogue: registers -> gmem
#pragma unroll
    for (int mi = 0; mi < 4; mi++) {
#pragma unroll
        for (int half = 0; half < 2; half++) {
            int r = row0 + wr * 64 + mi * 16 + gq + half * 8;
            if (r >= Nrows) continue;
#pragma unroll
            for (int ni = 0; ni < 4; ni++) {
                int c = c0 + wc * 32 + ni * 8 + tg * 2;
                float v0 = acc[mi][ni][half * 2 + 0];
                float v1 = acc[mi][ni][half * 2 + 1];
                if (BIAS) { v0 += bias[c]; v1 += bias[c + 1]; }
                if (RELU) { v0 = fmaxf(v0, 0.f); v1 = fmaxf(v1, 0.f); }
                size_t o = (size_t)r * C + c;
                if (WF32) *(float2*)(outf + o) = make_float2(v0, v1);
                if (WHILO) {
                    __nv_bfloat16 h0, l0, h1, l1;
                    f32_hilo(v0, h0, l0); f32_hilo(v1, h1, l1);
                    __nv_bfloat162 hh; hh.x = h0; hh.y = h1;
                    __nv_bfloat162 ll; ll.x = l0; ll.y = l1;
                    *(__nv_bfloat162*)(outhi + o) = hh;
                    *(__nv_bfloat162*)(outlo + o) = ll;
                }
            }
        }
    }
}

// ---------------- CSR build --------------------------------------------------
__global__ void hist_kernel(const int* __restrict__ dst, int* __restrict__ cnt, int E) {
    int e = blockIdx.x * blockDim.x + threadIdx.x;
    if (e < E) atomicAdd(&cnt[dst[e]], 1);
}

__global__ __launch_bounds__(1024)
void scan_kernel(const int* __restrict__ cnt, int* __restrict__ off, int n) {
    __shared__ int warp_sums[32];
    __shared__ int carry_s;
    const int tid  = threadIdx.x;
    const int wid  = tid >> 5;
    const int lane = tid & 31;
    if (tid == 0) carry_s = 0;
    __syncthreads();

    for (int base = 0; base < n; base += 1024) {
        int carry = carry_s;
        int idx = base + tid;
        int v = (idx < n) ? cnt[idx] : 0;
        int x = v;
#pragma unroll
        for (int o = 1; o < 32; o <<= 1) {
            int y = __shfl_up_sync(0xffffffffu, x, o);
            if (lane >= o) x += y;
        }
        if (lane == 31) warp_sums[wid] = x;
        __syncthreads();
        if (tid < 32) {
            int w = warp_sums[tid];
#pragma unroll
            for (int o = 1; o < 32; o <<= 1) {
                int y = __shfl_up_sync(0xffffffffu, w, o);
                if (tid >= o) w += y;
            }
            warp_sums[tid] = w;
        }
        __syncthreads();
        int pre  = (wid > 0) ? warp_sums[wid - 1] : 0;
        int incl = x + pre + carry;
        if (idx < n) off[idx] = incl - v;
        __syncthreads();
        if (tid == 1023) carry_s = incl;
        __syncthreads();
    }
    if (tid == 0) off[n] = carry_s;
}

__global__ void fill_kernel(const int* __restrict__ dst, const int* __restrict__ src,
                            int* __restrict__ cursor, int* __restrict__ slist, int E) {
    int e = blockIdx.x * blockDim.x + threadIdx.x;
    if (e < E) {
        int p = atomicAdd(&cursor[dst[e]], 1);
        slist[p] = src[e];
    }
}

// ---------------- fused edge-softmax attention (one warp per dst node) -------
// 2-way ILP: two independent online-softmax accumulators, exact merge at end.
__global__ __launch_bounds__(256)
void attn_gather(const float* __restrict__ k, const float* __restrict__ q,
                 const float* __restrict__ v, const int* __restrict__ slist,
                 const int* __restrict__ off,
                 __nv_bfloat16* __restrict__ out_hi, __nv_bfloat16* __restrict__ out_lo,
                 int NQ) {
    int warp = (blockIdx.x * blockDim.x + threadIdx.x) >> 5;
    int lane = threadIdx.x & 31;
    if (warp >= NQ) return;
    const int d = warp;

    float4 qv = *(const float4*)(q + (size_t)d * D + lane * 4);
    int i0 = off[d], i1 = off[d + 1];

    float mA = -1e30f, sA = 0.f, mB = -1e30f, sB = 0.f;
    float4 aA = make_float4(0.f, 0.f, 0.f, 0.f);
    float4 aB = make_float4(0.f, 0.f, 0.f, 0.f);

    int i = i0;
    for (; i + 1 < i1; i += 2) {
        int s0 = slist[i], s1 = slist[i + 1];
        float4 k0 = *(const float4*)(k + (size_t)s0 * D + lane * 4);
        float4 k1 = *(const float4*)(k + (size_t)s1 * D + lane * 4);
        float4 v0 = *(const float4*)(v + (size_t)s0 * D + lane * 4);
        float4 v1 = *(const float4*)(v + (size_t)s1 * D + lane * 4);
        float d0 = k0.x * qv.x + k0.y * qv.y + k0.z * qv.z + k0.w * qv.w;
        float d1 = k1.x * qv.x + k1.y * qv.y + k1.z * qv.z + k1.w * qv.w;
        d0 += __shfl_xor_sync(0xffffffffu, d0, 1);
        d1 += __shfl_xor_sync(0xffffffffu, d1, 1);
        d0 += __shfl_xor_sync(0xffffffffu, d0, 2);
        d1 += __shfl_xor_sync(0xffffffffu, d1, 2);
        float x0 = d0 * 0.25f, x1 = d1 * 0.25f;
        float mn0 = fmaxf(mA, x0);
        float mn1 = fmaxf(mB, x1);
        float c0 = __expf(mA - mn0), p0 = __expf(x0 - mn0);
        float c1 = __expf(mB - mn1), p1 = __expf(x1 - mn1);
        sA = sA * c0 + p0;
        sB = sB * c1 + p1;
        aA.x = aA.x * c0 + p0 * v0.x;  aB.x = aB.x * c1 + p1 * v1.x;
        aA.y = aA.y * c0 + p0 * v0.y;  aB.y = aB.y * c1 + p1 * v1.y;
        aA.z = aA.z * c0 + p0 * v0.z;  aB.z = aB.z * c1 + p1 * v1.z;
        aA.w = aA.w * c0 + p0 * v0.w;  aB.w = aB.w * c1 + p1 * v1.w;
        mA = mn0; mB = mn1;
    }
    if (i < i1) {
        int s0 = slist[i];
        float4 k0 = *(const float4*)(k + (size_t)s0 * D + lane * 4);
        float4 v0 = *(const float4*)(v + (size_t)s0 * D + lane * 4);
        float d0 = k0.x * qv.x + k0.y * qv.y + k0.z * qv.z + k0.w * qv.w;
        d0 += __shfl_xor_sync(0xffffffffu, d0, 1);
        d0 += __shfl_xor_sync(0xffffffffu, d0, 2);
        float x0 = d0 * 0.25f;
        float mn0 = fmaxf(mA, x0);
        float c0 = __expf(mA - mn0), p0 = __expf(x0 - mn0);
        sA = sA * c0 + p0;
        aA.x = aA.x * c0 + p0 * v0.x;
        aA.y = aA.y * c0 + p0 * v0.y;
        aA.z = aA.z * c0 + p0 * v0.z;
        aA.w = aA.w * c0 + p0 * v0.w;
        mA = mn0;
    }
    // merge the two accumulators (exact)
    float mn = fmaxf(mA, mB);
    float cA = __expf(mA - mn), cB = __expf(mB - mn);
    float sden = sA * cA + sB * cB;
    float4 acc;
    acc.x = aA.x * cA + aB.x * cB;
    acc.y = aA.y * cA + aB.y * cB;
    acc.z = aA.z * cA + aB.z * cB;
    acc.w = aA.w * cA + aB.w * cB;

    float inv = (sden > 0.f) ? (1.f / sden) : 0.f;
    float4 o = make_float4(acc.x * inv, acc.y * inv, acc.z * inv, acc.w * inv);
    __nv_bfloat16 h[4], l[4];
    f32_hilo(o.x, h[0], l[0]); f32_hilo(o.y, h[1], l[1]);
    f32_hilo(o.z, h[2], l[2]); f32_hilo(o.w, h[3], l[3]);
    size_t ob = (size_t)d * D + lane * 4;
    *(uint2*)(out_hi + ob) = *(uint2*)h;
    *(uint2*)(out_lo + ob) = *(uint2*)l;
}

// ---------------- residual add + layernorm ------------------------------------
template<bool WHILO>
__global__ void add_ln_kernel(const float* __restrict__ a, const float* __restrict__ b,
                              const float* __restrict__ gamma, const float* __restrict__ beta,
                              float* __restrict__ out,
                              __nv_bfloat16* __restrict__ out_hi,
                              __nv_bfloat16* __restrict__ out_lo) {
    int row = blockIdx.x;
    int t   = threadIdx.x;
    float x = a[(size_t)row * D + t] + b[(size_t)row * D + t];
    float s = x, s2 = x * x;
#pragma unroll
    for (int off = 16; off; off >>= 1) {
        s  += __shfl_xor_sync(0xffffffffu, s,  off);
        s2 += __shfl_xor_sync(0xffffffffu, s2, off);
    }
    __shared__ float ps[4], ps2[4];
    if ((t & 31) == 0) { ps[t >> 5] = s; ps2[t >> 5] = s2; }
    __syncthreads();
    s  = ps[0]  + ps[1]  + ps[2]  + ps[3];
    s2 = ps2[0] + ps2[1] + ps2[2] + ps2[3];
    float mu  = s * (1.f / 128.f);
    float var = s2 * (1.f / 128.f) - mu * mu;
    float invs = rsqrtf(var + 1e-5f);
    float y = (x - mu) * invs * gamma[t] + beta[t];
    out[(size_t)row * D + t] = y;
    if (WHILO) {
        __nv_bfloat16 h, l;
        f32_hilo(y, h, l);
        out_hi[(size_t)row * D + t] = h;
        out_lo[(size_t)row * D + t] = l;
    }
}

// ---------------- launch -----------------------------------------------------
extern "C" void kernel_launch(void* const* d_in, const int* in_sizes, int n_in,
                              void* d_out, int out_size) {
    const float* q_feat  = (const float*)d_in[0];
    const float* kv_feat = (const float*)d_in[1];
    const int*   src     = (const int*)d_in[2];
    const int*   dst     = (const int*)d_in[3];
    const float* Wq      = (const float*)d_in[4];
    const float* Wk      = (const float*)d_in[5];
    const float* Wv      = (const float*)d_in[6];
    const float* Wo      = (const float*)d_in[7];
    const float* W1      = (const float*)d_in[8];
    const float* bf1     = (const float*)d_in[9];
    const float* W2      = (const float*)d_in[10];
    const float* bf2     = (const float*)d_in[11];
    const float* ln1_g   = (const float*)d_in[12];
    const float* ln1_b   = (const float*)d_in[13];
    const float* ln2_g   = (const float*)d_in[14];
    const float* ln2_b   = (const float*)d_in[15];

    const int NQ  = in_sizes[0] / D;
    const int NKV = in_sizes[1] / D;
    const int E   = in_sizes[2];

    float *qp, *kp, *vp, *sap, *featp, *ffp;
    __nv_bfloat16 *qfh, *qfl, *kvfh, *kvfl, *ath, *atl, *fth, *ftl, *hdh, *hdl;
    __nv_bfloat16 *wqh, *wql, *wkh, *wkl, *wvh, *wvl, *woh, *wol, *w1h, *w1l, *w2h, *w2l;
    int *cntp, *offp, *curp, *slistp;
    cudaGetSymbolAddress((void**)&qp,    g_q);
    cudaGetSymbolAddress((void**)&kp,    g_k);
    cudaGetSymbolAddress((void**)&vp,    g_v);
    cudaGetSymbolAddress((void**)&sap,   g_sa);
    cudaGetSymbolAddress((void**)&featp, g_feat);
    cudaGetSymbolAddress((void**)&ffp,   g_ff);
    cudaGetSymbolAddress((void**)&qfh,   g_qf_hi);   cudaGetSymbolAddress((void**)&qfl, g_qf_lo);
    cudaGetSymbolAddress((void**)&kvfh,  g_kvf_hi);  cudaGetSymbolAddress((void**)&kvfl, g_kvf_lo);
    cudaGetSymbolAddress((void**)&ath,   g_attn_hi); cudaGetSymbolAddress((void**)&atl, g_attn_lo);
    cudaGetSymbolAddress((void**)&fth,   g_feat_hi); cudaGetSymbolAddress((void**)&ftl, g_feat_lo);
    cudaGetSymbolAddress((void**)&hdh,   g_hid_hi);  cudaGetSymbolAddress((void**)&hdl, g_hid_lo);
    cudaGetSymbolAddress((void**)&wqh,   g_Wq_hi);   cudaGetSymbolAddress((void**)&wql, g_Wq_lo);
    cudaGetSymbolAddress((void**)&wkh,   g_Wk_hi);   cudaGetSymbolAddress((void**)&wkl, g_Wk_lo);
    cudaGetSymbolAddress((void**)&wvh,   g_Wv_hi);   cudaGetSymbolAddress((void**)&wvl, g_Wv_lo);
    cudaGetSymbolAddress((void**)&woh,   g_Wo_hi);   cudaGetSymbolAddress((void**)&wol, g_Wo_lo);
    cudaGetSymbolAddress((void**)&w1h,   g_W1_hi);   cudaGetSymbolAddress((void**)&w1l, g_W1_lo);
    cudaGetSymbolAddress((void**)&w2h,   g_W2_hi);   cudaGetSymbolAddress((void**)&w2l, g_W2_lo);
    cudaGetSymbolAddress((void**)&cntp,  g_cnt);
    cudaGetSymbolAddress((void**)&offp,  g_off);
    cudaGetSymbolAddress((void**)&curp,  g_cursor);
    cudaGetSymbolAddress((void**)&slistp, g_slist);

    cudaFuncSetAttribute(gemm_mma<false, false, true,  false>,
                         cudaFuncAttributeMaxDynamicSharedMemorySize, GEMM_SMEM);
    cudaFuncSetAttribute(gemm_mma<true,  true,  false, true>,
                         cudaFuncAttributeMaxDynamicSharedMemorySize, GEMM_SMEM);
    cudaFuncSetAttribute(gemm_mma<true,  false, true,  false>,
                         cudaFuncAttributeMaxDynamicSharedMemorySize, GEMM_SMEM);

    // conversions (2 launches)
    int ntot = (NQ + NKV) * D;
    conv_inputs<<<(ntot + 255) / 256, 256>>>(q_feat, kv_feat, qfh, qfl, kvfh, kvfl, NQ * D, ntot);
    conv_weights<<<768, 256>>>(Wq, Wk, Wv, Wo, W1, W2,
                               wqh, wql, wkh, wkl, wvh, wvl, woh, wol, w1h, w1l, w2h, w2l);

    // CSR build (dst-grouped, stores src values directly)
    cudaMemsetAsync(cntp, 0, (size_t)NQ * sizeof(int));
    int eb = (E + 255) / 256;
    hist_kernel<<<eb, 256>>>(dst, cntp, E);
    scan_kernel<<<1, 1024>>>(cntp, offp, NQ);
    cudaMemcpyAsync(curp, offp, (size_t)NQ * sizeof(int), cudaMemcpyDeviceToDevice);
    fill_kernel<<<eb, 256>>>(dst, src, curp, slistp, E);

    const int MTq  = (NQ + 127) / 128;
    const int MTkv = (NKV + 127) / 128;

    // projections (tensor core)
    gemm_mma<false, false, true, false><<<dim3(MTq, 1), 256, GEMM_SMEM>>>(
        qfh, qfl, wqh, wql, nullptr, qp, nullptr, nullptr, NQ, D, D);
    gemm_mma<false, false, true, false><<<dim3(MTkv, 1), 256, GEMM_SMEM>>>(
        kvfh, kvfl, wkh, wkl, nullptr, kp, nullptr, nullptr, NKV, D, D);
    gemm_mma<false, false, true, false><<<dim3(MTkv, 1), 256, GEMM_SMEM>>>(
        kvfh, kvfl, wvh, wvl, nullptr, vp, nullptr, nullptr, NKV, D, D);

    // fused one-pass edge-softmax attention (one warp per dst)
    int ablocks = (NQ * 32 + 255) / 256;
    attn_gather<<<ablocks, 256>>>(kp, qp, vp, slistp, offp, ath, atl, NQ);

    // output projection + residual LN
    gemm_mma<false, false, true, false><<<dim3(MTq, 1), 256, GEMM_SMEM>>>(
        ath, atl, woh, wol, nullptr, sap, nullptr, nullptr, NQ, D, D);
    add_ln_kernel<true><<<NQ, 128>>>(q_feat, sap, ln1_g, ln1_b, featp, fth, ftl);

    // FFN
    gemm_mma<true, true, false, true><<<dim3(MTq, 4), 256, GEMM_SMEM>>>(
        fth, ftl, w1h, w1l, bf1, nullptr, hdh, hdl, NQ, DF, D);
    gemm_mma<true, false, true, false><<<dim3(MTq, 1), 256, GEMM_SMEM>>>(
        hdh, hdl, w2h, w2l, bf2, ffp, nullptr, nullptr, NQ, D, DF);

    // final residual LN -> output
    add_ln_kernel<false><<<NQ, 128>>>(featp, ffp, ln2_g, ln2_b, (float*)d_out, nullptr, nullptr);
}

// round 6
// speedup vs baseline: 3.3979x; 1.0330x over previous
#include <cuda_runtime.h>
#include <cuda_bf16.h>
#include <cstdint>

#define D   128
#define H   8
#define DH  16
#define DF  512
#define NQ_MAX  20000
#define NKV_MAX 20000
#define E_MAX   640000

// ---------------- scratch (device globals; no allocations allowed) ----------
__device__ float g_q[NQ_MAX * D];
__device__ float g_k[NKV_MAX * D];
__device__ float g_v[NKV_MAX * D];
__device__ float g_sa[NQ_MAX * D];
__device__ float g_feat[NQ_MAX * D];
__device__ float g_ff[NQ_MAX * D];

__device__ __align__(128) __nv_bfloat16 g_qf_hi[NQ_MAX * D];
__device__ __align__(128) __nv_bfloat16 g_qf_lo[NQ_MAX * D];
__device__ __align__(128) __nv_bfloat16 g_kvf_hi[NKV_MAX * D];
__device__ __align__(128) __nv_bfloat16 g_kvf_lo[NKV_MAX * D];
__device__ __align__(128) __nv_bfloat16 g_attn_hi[NQ_MAX * D];
__device__ __align__(128) __nv_bfloat16 g_attn_lo[NQ_MAX * D];
__device__ __align__(128) __nv_bfloat16 g_feat_hi[NQ_MAX * D];
__device__ __align__(128) __nv_bfloat16 g_feat_lo[NQ_MAX * D];
__device__ __align__(128) __nv_bfloat16 g_hid_hi[NQ_MAX * DF];
__device__ __align__(128) __nv_bfloat16 g_hid_lo[NQ_MAX * DF];
__device__ __align__(128) __nv_bfloat16 g_Wq_hi[D * D],  g_Wq_lo[D * D];
__device__ __align__(128) __nv_bfloat16 g_Wk_hi[D * D],  g_Wk_lo[D * D];
__device__ __align__(128) __nv_bfloat16 g_Wv_hi[D * D],  g_Wv_lo[D * D];
__device__ __align__(128) __nv_bfloat16 g_Wo_hi[D * D],  g_Wo_lo[D * D];
__device__ __align__(128) __nv_bfloat16 g_W1_hi[DF * D], g_W1_lo[DF * D];
__device__ __align__(128) __nv_bfloat16 g_W2_hi[D * DF], g_W2_lo[D * DF];

// CSR scratch
__device__ int g_cnt[NQ_MAX];
__device__ int g_off[NQ_MAX + 1];
__device__ int g_cursor[NQ_MAX];
__device__ int g_slist[E_MAX];

// ---------------- helpers ------------------------------------------------------
__device__ __forceinline__ uint32_t smem_u32(const void* p) {
    uint32_t a;
    asm("{ .reg .u64 t; cvta.to.shared.u64 t, %1; cvt.u32.u64 %0, t; }" : "=r"(a) : "l"(p));
    return a;
}
__device__ __forceinline__ void f32_hilo(float x, __nv_bfloat16& h, __nv_bfloat16& l) {
    h = __float2bfloat16(x);
    l = __float2bfloat16(x - __bfloat162float(h));
}
__device__ __forceinline__ void mma16816(float* c, const uint32_t* a, const uint32_t* b) {
    asm volatile(
        "mma.sync.aligned.m16n8k16.row.col.f32.bf16.bf16.f32 "
        "{%0,%1,%2,%3}, {%4,%5,%6,%7}, {%8,%9}, {%0,%1,%2,%3};"
        : "+f"(c[0]), "+f"(c[1]), "+f"(c[2]), "+f"(c[3])
        : "r"(a[0]), "r"(a[1]), "r"(a[2]), "r"(a[3]), "r"(b[0]), "r"(b[1]));
}

// ---------------- conversions -------------------------------------------------
__global__ void conv_inputs(const float* __restrict__ qf, const float* __restrict__ kvf,
                            int nq, int ntot) {
    int i = blockIdx.x * blockDim.x + threadIdx.x;
    if (i >= ntot) return;
    __nv_bfloat16 h, l;
    if (i < nq) {
        f32_hilo(qf[i], h, l);
        g_qf_hi[i] = h; g_qf_lo[i] = l;
    } else {
        int j = i - nq;
        f32_hilo(kvf[j], h, l);
        g_kvf_hi[j] = h; g_kvf_lo[j] = l;
    }
}

__global__ void conv_weights(const float* __restrict__ Wq, const float* __restrict__ Wk,
                             const float* __restrict__ Wv, const float* __restrict__ Wo,
                             const float* __restrict__ W1, const float* __restrict__ W2) {
    int i = blockIdx.x * blockDim.x + threadIdx.x;     // 0 .. 196607
    const float* src; __nv_bfloat16 *ho, *lo_; int r;
    if (i < 65536) {
        int which = i >> 14; r = i & 16383;
        if (which == 0)      { src = Wq; ho = g_Wq_hi; lo_ = g_Wq_lo; }
        else if (which == 1) { src = Wk; ho = g_Wk_hi; lo_ = g_Wk_lo; }
        else if (which == 2) { src = Wv; ho = g_Wv_hi; lo_ = g_Wv_lo; }
        else                 { src = Wo; ho = g_Wo_hi; lo_ = g_Wo_lo; }
    } else if (i < 131072) { r = i - 65536;  src = W1; ho = g_W1_hi; lo_ = g_W1_lo; }
    else                   { r = i - 131072; src = W2; ho = g_W2_hi; lo_ = g_W2_lo; }
    __nv_bfloat16 h, l;
    f32_hilo(src[r], h, l);
    ho[r] = h; lo_[r] = l;
}

// ---------------- tensor-core GEMM body: out[N][C] = X[N][K] @ W[C][K]^T -----
// bf16x3 split, mma.sync m16n8k16, 128x128 CTA tile, 8 warps (2x4 of 64x32).
// cp.async 2-stage pipeline, K-chunk 32, smem row stride 80B (conflict-free).
#define KSTB  80
#define BUF   (128 * KSTB)                 // 10240 bytes
#define STAGE (4 * BUF)                    // 40960 per stage
#define GEMM_SMEM (2 * STAGE)              // 81920 bytes

__device__ __forceinline__ void stage32(uint32_t sbase, int tid,
    const __nv_bfloat16* __restrict__ Ahi, const __nv_bfloat16* __restrict__ Alo,
    const __nv_bfloat16* __restrict__ Bhi, const __nv_bfloat16* __restrict__ Blo,
    int row0, int c0, int kc, int K, int Nrows) {
#pragma unroll
    for (int j = 0; j < 8; j++) {
        int id  = tid + (j << 8);
        int buf = id >> 9;
        int rem = id & 511;
        int r   = rem >> 2;
        int c16 = rem & 3;
        const __nv_bfloat16* g;
        int rg;
        if (buf == 0)      { g = Ahi; rg = min(row0 + r, Nrows - 1); }
        else if (buf == 1) { g = Alo; rg = min(row0 + r, Nrows - 1); }
        else if (buf == 2) { g = Bhi; rg = c0 + r; }
        else               { g = Blo; rg = c0 + r; }
        uint32_t daddr = sbase + buf * BUF + r * KSTB + c16 * 16;
        unsigned long long gsrc =
            (unsigned long long)__cvta_generic_to_global(g + (size_t)rg * K + kc + c16 * 8);
        asm volatile("cp.async.cg.shared.global [%0], [%1], 16;"
                     :: "r"(daddr), "l"(gsrc) : "memory");
    }
}

template<bool BIAS, bool RELU, bool WF32, bool WHILO>
__device__ __forceinline__ void gemm_body(
    char* smem,
    const __nv_bfloat16* __restrict__ Ahi, const __nv_bfloat16* __restrict__ Alo,
    const __nv_bfloat16* __restrict__ Bhi, const __nv_bfloat16* __restrict__ Blo,
    const float* __restrict__ bias,
    float* __restrict__ outf, __nv_bfloat16* __restrict__ outhi,
    __nv_bfloat16* __restrict__ outlo, int Nrows, int C, int K, int row0, int c0) {
    const uint32_t sb = smem_u32(smem);
    const int tid  = threadIdx.x;
    const int wid  = tid >> 5;
    const int lane = tid & 31;
    const int wr   = wid >> 2;
    const int wc   = wid & 3;
    const int gq   = lane >> 2;
    const int tg   = lane & 3;

    float acc[4][4][4];
#pragma unroll
    for (int mi = 0; mi < 4; mi++)
#pragma unroll
        for (int ni = 0; ni < 4; ni++)
#pragma unroll
            for (int t = 0; t < 4; t++) acc[mi][ni][t] = 0.f;

    const int NC = K >> 5;
    stage32(sb, tid, Ahi, Alo, Bhi, Blo, row0, c0, 0, K, Nrows);
    asm volatile("cp.async.commit_group;" ::: "memory");

    for (int ch = 0; ch < NC; ch++) {
        if (ch + 1 < NC) {
            stage32(sb + ((ch + 1) & 1) * STAGE, tid, Ahi, Alo, Bhi, Blo,
                    row0, c0, (ch + 1) << 5, K, Nrows);
            asm volatile("cp.async.commit_group;" ::: "memory");
            asm volatile("cp.async.wait_group 1;" ::: "memory");
        } else {
            asm volatile("cp.async.wait_group 0;" ::: "memory");
        }
        __syncthreads();

        const char* sAh = smem + (ch & 1) * STAGE;
        const char* sAl = sAh + BUF;
        const char* sBh = sAh + 2 * BUF;
        const char* sBl = sAh + 3 * BUF;

#pragma unroll
        for (int ks = 0; ks < 2; ks++) {
            const int kbyte = (ks << 5) + (tg << 2);
            uint32_t bh[4][2], bl[4][2];
#pragma unroll
            for (int ni = 0; ni < 4; ni++) {
                int n = wc * 32 + ni * 8 + gq;
                const char* pbh = sBh + n * KSTB + kbyte;
                const char* pbl = sBl + n * KSTB + kbyte;
                bh[ni][0] = *(const uint32_t*)(pbh);
                bh[ni][1] = *(const uint32_t*)(pbh + 16);
                bl[ni][0] = *(const uint32_t*)(pbl);
                bl[ni][1] = *(const uint32_t*)(pbl + 16);
            }
#pragma unroll
            for (int mi = 0; mi < 4; mi++) {
                int r = wr * 64 + mi * 16 + gq;
                const char* pah = sAh + r * KSTB + kbyte;
                const char* pal = sAl + r * KSTB + kbyte;
                uint32_t ah[4], al[4];
                ah[0] = *(const uint32_t*)(pah);
                ah[1] = *(const uint32_t*)(pah + 8 * KSTB);
                ah[2] = *(const uint32_t*)(pah + 16);
                ah[3] = *(const uint32_t*)(pah + 8 * KSTB + 16);
                al[0] = *(const uint32_t*)(pal);
                al[1] = *(const uint32_t*)(pal + 8 * KSTB);
                al[2] = *(const uint32_t*)(pal + 16);
                al[3] = *(const uint32_t*)(pal + 8 * KSTB + 16);
#pragma unroll
                for (int ni = 0; ni < 4; ni++) {
                    mma16816(acc[mi][ni], ah, bh[ni]);
                    mma16816(acc[mi][ni], ah, bl[ni]);
                    mma16816(acc[mi][ni], al, bh[ni]);
                }
            }
        }
        __syncthreads();
    }

    // epilogue: registers -> gmem
#pragma unroll
    for (int mi = 0; mi < 4; mi++) {
#pragma unroll
        for (int half = 0; half < 2; half++) {
            int r = row0 + wr * 64 + mi * 16 + gq + half * 8;
            if (r >= Nrows) continue;
#pragma unroll
            for (int ni = 0; ni < 4; ni++) {
                int c = c0 + wc * 32 + ni * 8 + tg * 2;
                float v0 = acc[mi][ni][half * 2 + 0];
                float v1 = acc[mi][ni][half * 2 + 1];
                if (BIAS) { v0 += bias[c]; v1 += bias[c + 1]; }
                if (RELU) { v0 = fmaxf(v0, 0.f); v1 = fmaxf(v1, 0.f); }
                size_t o = (size_t)r * C + c;
                if (WF32) *(float2*)(outf + o) = make_float2(v0, v1);
                if (WHILO) {
                    __nv_bfloat16 h0, l0, h1, l1;
                    f32_hilo(v0, h0, l0); f32_hilo(v1, h1, l1);
                    __nv_bfloat162 hh; hh.x = h0; hh.y = h1;
                    __nv_bfloat162 ll; ll.x = l0; ll.y = l1;
                    *(__nv_bfloat162*)(outhi + o) = hh;
                    *(__nv_bfloat162*)(outlo + o) = ll;
                }
            }
        }
    }
}

template<bool BIAS, bool RELU, bool WF32, bool WHILO>
__global__ void __launch_bounds__(256, 2)
gemm_mma(const __nv_bfloat16* __restrict__ Ahi, const __nv_bfloat16* __restrict__ Alo,
         const __nv_bfloat16* __restrict__ Bhi, const __nv_bfloat16* __restrict__ Blo,
         const float* __restrict__ bias,
         float* __restrict__ outf, __nv_bfloat16* __restrict__ outhi,
         __nv_bfloat16* __restrict__ outlo, int Nrows, int C, int K) {
    extern __shared__ char smem[];
    gemm_body<BIAS, RELU, WF32, WHILO>(smem, Ahi, Alo, Bhi, Blo, bias,
                                       outf, outhi, outlo, Nrows, C, K,
                                       blockIdx.x * 128, blockIdx.y * 128);
}

// fused q/k/v projections: blockIdx.y selects which GEMM; operands are globals
__global__ void __launch_bounds__(256, 2)
proj_qkv(int NQ, int NKV) {
    extern __shared__ char smem[];
    const int row0 = blockIdx.x * 128;
    if (blockIdx.y == 0) {
        if (row0 >= NQ) return;
        gemm_body<false, false, true, false>(smem, g_qf_hi, g_qf_lo, g_Wq_hi, g_Wq_lo,
                                             nullptr, g_q, nullptr, nullptr, NQ, D, D, row0, 0);
    } else if (blockIdx.y == 1) {
        if (row0 >= NKV) return;
        gemm_body<false, false, true, false>(smem, g_kvf_hi, g_kvf_lo, g_Wk_hi, g_Wk_lo,
                                             nullptr, g_k, nullptr, nullptr, NKV, D, D, row0, 0);
    } else {
        if (row0 >= NKV) return;
        gemm_body<false, false, true, false>(smem, g_kvf_hi, g_kvf_lo, g_Wv_hi, g_Wv_lo,
                                             nullptr, g_v, nullptr, nullptr, NKV, D, D, row0, 0);
    }
}

// ---------------- CSR build --------------------------------------------------
__global__ void hist_kernel(const int* __restrict__ dst, int* __restrict__ cnt, int E) {
    int e = blockIdx.x * blockDim.x + threadIdx.x;
    if (e < E) atomicAdd(&cnt[dst[e]], 1);
}

// single-block scan: thread t owns a contiguous chunk; serial sum -> block scan
// of totals -> serial prefix writeback. Writes off, cursor, and off[n].
__global__ __launch_bounds__(1024)
void scan_kernel(const int* __restrict__ cnt, int* __restrict__ off,
                 int* __restrict__ cursor, int n) {
    __shared__ int wsum[32];
    const int tid  = threadIdx.x;
    const int lane = tid & 31;
    const int wid  = tid >> 5;
    const int chunk = (n + 1023) >> 10;
    const int s = tid * chunk;
    const int e = min(s + chunk, n);

    int sum = 0;
    for (int i = s; i < e; i++) sum += cnt[i];

    int x = sum;
#pragma unroll
    for (int o = 1; o < 32; o <<= 1) {
        int y = __shfl_up_sync(0xffffffffu, x, o);
        if (lane >= o) x += y;
    }
    if (lane == 31) wsum[wid] = x;
    __syncthreads();
    if (tid < 32) {
        int w = wsum[tid];
#pragma unroll
        for (int o = 1; o < 32; o <<= 1) {
            int y = __shfl_up_sync(0xffffffffu, w, o);
            if (tid >= o) w += y;
        }
        wsum[tid] = w;
    }
    __syncthreads();

    int run = x - sum + (wid > 0 ? wsum[wid - 1] : 0);   // exclusive prefix
    for (int i = s; i < e; i++) {
        off[i] = run;
        cursor[i] = run;
        run += cnt[i];
    }
    if (tid == 1023) off[n] = run;
}

__global__ void fill_kernel(const int* __restrict__ dst, const int* __restrict__ src,
                            int* __restrict__ cursor, int* __restrict__ slist, int E) {
    int e = blockIdx.x * blockDim.x + threadIdx.x;
    if (e < E) {
        int p = atomicAdd(&cursor[dst[e]], 1);
        slist[p] = src[e];
    }
}

// ---------------- fused edge-softmax attention (one warp per dst node) -------
__global__ __launch_bounds__(256)
void attn_gather(const float* __restrict__ k, const float* __restrict__ q,
                 const float* __restrict__ v, const int* __restrict__ slist,
                 const int* __restrict__ off,
                 __nv_bfloat16* __restrict__ out_hi, __nv_bfloat16* __restrict__ out_lo,
                 int NQ) {
    int warp = (blockIdx.x * blockDim.x + threadIdx.x) >> 5;
    int lane = threadIdx.x & 31;
    if (warp >= NQ) return;
    const int d = warp;

    float4 qv = *(const float4*)(q + (size_t)d * D + lane * 4);
    int i0 = off[d], i1 = off[d + 1];

    float mA = -1e30f, sA = 0.f, mB = -1e30f, sB = 0.f;
    float4 aA = make_float4(0.f, 0.f, 0.f, 0.f);
    float4 aB = make_float4(0.f, 0.f, 0.f, 0.f);

    int i = i0;
    for (; i + 1 < i1; i += 2) {
        int s0 = slist[i], s1 = slist[i + 1];
        float4 k0 = *(const float4*)(k + (size_t)s0 * D + lane * 4);
        float4 k1 = *(const float4*)(k + (size_t)s1 * D + lane * 4);
        float4 v0 = *(const float4*)(v + (size_t)s0 * D + lane * 4);
        float4 v1 = *(const float4*)(v + (size_t)s1 * D + lane * 4);
        float d0 = k0.x * qv.x + k0.y * qv.y + k0.z * qv.z + k0.w * qv.w;
        float d1 = k1.x * qv.x + k1.y * qv.y + k1.z * qv.z + k1.w * qv.w;
        d0 += __shfl_xor_sync(0xffffffffu, d0, 1);
        d1 += __shfl_xor_sync(0xffffffffu, d1, 1);
        d0 += __shfl_xor_sync(0xffffffffu, d0, 2);
        d1 += __shfl_xor_sync(0xffffffffu, d1, 2);
        float x0 = d0 * 0.25f, x1 = d1 * 0.25f;
        float mn0 = fmaxf(mA, x0);
        float mn1 = fmaxf(mB, x1);
        float c0 = __expf(mA - mn0), p0 = __expf(x0 - mn0);
        float c1 = __expf(mB - mn1), p1 = __expf(x1 - mn1);
        sA = sA * c0 + p0;
        sB = sB * c1 + p1;
        aA.x = aA.x * c0 + p0 * v0.x;  aB.x = aB.x * c1 + p1 * v1.x;
        aA.y = aA.y * c0 + p0 * v0.y;  aB.y = aB.y * c1 + p1 * v1.y;
        aA.z = aA.z * c0 + p0 * v0.z;  aB.z = aB.z * c1 + p1 * v1.z;
        aA.w = aA.w * c0 + p0 * v0.w;  aB.w = aB.w * c1 + p1 * v1.w;
        mA = mn0; mB = mn1;
    }
    if (i < i1) {
        int s0 = slist[i];
        float4 k0 = *(const float4*)(k + (size_t)s0 * D + lane * 4);
        float4 v0 = *(const float4*)(v + (size_t)s0 * D + lane * 4);
        float d0 = k0.x * qv.x + k0.y * qv.y + k0.z * qv.z + k0.w * qv.w;
        d0 += __shfl_xor_sync(0xffffffffu, d0, 1);
        d0 += __shfl_xor_sync(0xffffffffu, d0, 2);
        float x0 = d0 * 0.25f;
        float mn0 = fmaxf(mA, x0);
        float c0 = __expf(mA - mn0), p0 = __expf(x0 - mn0);
        sA = sA * c0 + p0;
        aA.x = aA.x * c0 + p0 * v0.x;
        aA.y = aA.y * c0 + p0 * v0.y;
        aA.z = aA.z * c0 + p0 * v0.z;
        aA.w = aA.w * c0 + p0 * v0.w;
        mA = mn0;
    }
    float mn = fmaxf(mA, mB);
    float cA = __expf(mA - mn), cB = __expf(mB - mn);
    float sden = sA * cA + sB * cB;
    float4 acc;
    acc.x = aA.x * cA + aB.x * cB;
    acc.y = aA.y * cA + aB.y * cB;
    acc.z = aA.z * cA + aB.z * cB;
    acc.w = aA.w * cA + aB.w * cB;

    float inv = (sden > 0.f) ? (1.f / sden) : 0.f;
    float4 o = make_float4(acc.x * inv, acc.y * inv, acc.z * inv, acc.w * inv);
    __nv_bfloat16 h[4], l[4];
    f32_hilo(o.x, h[0], l[0]); f32_hilo(o.y, h[1], l[1]);
    f32_hilo(o.z, h[2], l[2]); f32_hilo(o.w, h[3], l[3]);
    size_t ob = (size_t)d * D + lane * 4;
    *(uint2*)(out_hi + ob) = *(uint2*)h;
    *(uint2*)(out_lo + ob) = *(uint2*)l;
}

// ---------------- residual add + layernorm ------------------------------------
template<bool WHILO>
__global__ void add_ln_kernel(const float* __restrict__ a, const float* __restrict__ b,
                              const float* __restrict__ gamma, const float* __restrict__ beta,
                              float* __restrict__ out,
                              __nv_bfloat16* __restrict__ out_hi,
                              __nv_bfloat16* __restrict__ out_lo) {
    int row = blockIdx.x;
    int t   = threadIdx.x;
    float x = a[(size_t)row * D + t] + b[(size_t)row * D + t];
    float s = x, s2 = x * x;
#pragma unroll
    for (int off = 16; off; off >>= 1) {
        s  += __shfl_xor_sync(0xffffffffu, s,  off);
        s2 += __shfl_xor_sync(0xffffffffu, s2, off);
    }
    __shared__ float ps[4], ps2[4];
    if ((t & 31) == 0) { ps[t >> 5] = s; ps2[t >> 5] = s2; }
    __syncthreads();
    s  = ps[0]  + ps[1]  + ps[2]  + ps[3];
    s2 = ps2[0] + ps2[1] + ps2[2] + ps2[3];
    float mu  = s * (1.f / 128.f);
    float var = s2 * (1.f / 128.f) - mu * mu;
    float invs = rsqrtf(var + 1e-5f);
    float y = (x - mu) * invs * gamma[t] + beta[t];
    out[(size_t)row * D + t] = y;
    if (WHILO) {
        __nv_bfloat16 h, l;
        f32_hilo(y, h, l);
        out_hi[(size_t)row * D + t] = h;
        out_lo[(size_t)row * D + t] = l;
    }
}

// ---------------- launch -----------------------------------------------------
extern "C" void kernel_launch(void* const* d_in, const int* in_sizes, int n_in,
                              void* d_out, int out_size) {
    const float* q_feat  = (const float*)d_in[0];
    const float* kv_feat = (const float*)d_in[1];
    const int*   src     = (const int*)d_in[2];
    const int*   dst     = (const int*)d_in[3];
    const float* Wq      = (const float*)d_in[4];
    const float* Wk      = (const float*)d_in[5];
    const float* Wv      = (const float*)d_in[6];
    const float* Wo      = (const float*)d_in[7];
    const float* W1      = (const float*)d_in[8];
    const float* bf1     = (const float*)d_in[9];
    const float* W2      = (const float*)d_in[10];
    const float* bf2     = (const float*)d_in[11];
    const float* ln1_g   = (const float*)d_in[12];
    const float* ln1_b   = (const float*)d_in[13];
    const float* ln2_g   = (const float*)d_in[14];
    const float* ln2_b   = (const float*)d_in[15];

    const int NQ  = in_sizes[0] / D;
    const int NKV = in_sizes[1] / D;
    const int E   = in_sizes[2];

    float *qp, *kp, *vp, *sap, *featp, *ffp;
    __nv_bfloat16 *ath, *atl, *fth, *ftl, *hdh, *hdl;
    __nv_bfloat16 *woh, *wol, *w1h, *w1l, *w2h, *w2l;
    int *cntp, *offp, *curp, *slistp;
    cudaGetSymbolAddress((void**)&qp,    g_q);
    cudaGetSymbolAddress((void**)&kp,    g_k);
    cudaGetSymbolAddress((void**)&vp,    g_v);
    cudaGetSymbolAddress((void**)&sap,   g_sa);
    cudaGetSymbolAddress((void**)&featp, g_feat);
    cudaGetSymbolAddress((void**)&ffp,   g_ff);
    cudaGetSymbolAddress((void**)&ath,   g_attn_hi); cudaGetSymbolAddress((void**)&atl, g_attn_lo);
    cudaGetSymbolAddress((void**)&fth,   g_feat_hi); cudaGetSymbolAddress((void**)&ftl, g_feat_lo);
    cudaGetSymbolAddress((void**)&hdh,   g_hid_hi);  cudaGetSymbolAddress((void**)&hdl, g_hid_lo);
    cudaGetSymbolAddress((void**)&woh,   g_Wo_hi);   cudaGetSymbolAddress((void**)&wol, g_Wo_lo);
    cudaGetSymbolAddress((void**)&w1h,   g_W1_hi);   cudaGetSymbolAddress((void**)&w1l, g_W1_lo);
    cudaGetSymbolAddress((void**)&w2h,   g_W2_hi);   cudaGetSymbolAddress((void**)&w2l, g_W2_lo);
    cudaGetSymbolAddress((void**)&cntp,  g_cnt);
    cudaGetSymbolAddress((void**)&offp,  g_off);
    cudaGetSymbolAddress((void**)&curp,  g_cursor);
    cudaGetSymbolAddress((void**)&slistp, g_slist);

    cudaFuncSetAttribute(proj_qkv,
                         cudaFuncAttributeMaxDynamicSharedMemorySize, GEMM_SMEM);
    cudaFuncSetAttribute(gemm_mma<false, false, true,  false>,
                         cudaFuncAttributeMaxDynamicSharedMemorySize, GEMM_SMEM);
    cudaFuncSetAttribute(gemm_mma<true,  true,  false, true>,
                         cudaFuncAttributeMaxDynamicSharedMemorySize, GEMM_SMEM);
    cudaFuncSetAttribute(gemm_mma<true,  false, true,  false>,
                         cudaFuncAttributeMaxDynamicSharedMemorySize, GEMM_SMEM);

    // conversions (2 launches)
    int ntot = (NQ + NKV) * D;
    conv_inputs<<<(ntot + 255) / 256, 256>>>(q_feat, kv_feat, NQ * D, ntot);
    conv_weights<<<768, 256>>>(Wq, Wk, Wv, Wo, W1, W2);

    // CSR build (dst-grouped, stores src values directly)
    cudaMemsetAsync(cntp, 0, (size_t)NQ * sizeof(int));
    int eb = (E + 255) / 256;
    hist_kernel<<<eb, 256>>>(dst, cntp, E);
    scan_kernel<<<1, 1024>>>(cntp, offp, curp, NQ);
    fill_kernel<<<eb, 256>>>(dst, src, curp, slistp, E);

    const int MTq  = (NQ + 127) / 128;
    const int MTkv = (NKV + 127) / 128;
    const int MTmax = MTq > MTkv ? MTq : MTkv;

    // fused q/k/v projections (one launch)
    proj_qkv<<<dim3(MTmax, 3), 256, GEMM_SMEM>>>(NQ, NKV);

    // fused one-pass edge-softmax attention (one warp per dst)
    int ablocks = (NQ * 32 + 255) / 256;
    attn_gather<<<ablocks, 256>>>(kp, qp, vp, slistp, offp, ath, atl, NQ);

    // output projection + residual LN
    gemm_mma<false, false, true, false><<<dim3(MTq, 1), 256, GEMM_SMEM>>>(
        ath, atl, woh, wol, nullptr, sap, nullptr, nullptr, NQ, D, D);
    add_ln_kernel<true><<<NQ, 128>>>(q_feat, sap, ln1_g, ln1_b, featp, fth, ftl);

    // FFN
    gemm_mma<true, true, false, true><<<dim3(MTq, 4), 256, GEMM_SMEM>>>(
        fth, ftl, w1h, w1l, bf1, nullptr, hdh, hdl, NQ, DF, D);
    gemm_mma<true, false, true, false><<<dim3(MTq, 1), 256, GEMM_SMEM>>>(
        hdh, hdl, w2h, w2l, bf2, ffp, nullptr, nullptr, NQ, D, DF);

    // final residual LN -> output
    add_ln_kernel<false><<<NQ, 128>>>(featp, ffp, ln2_g, ln2_b, (float*)d_out, nullptr, nullptr);
}

// round 7
// speedup vs baseline: 3.5407x; 1.0420x over previous
#include <cuda_runtime.h>
#include <cuda_bf16.h>
#include <cstdint>

#define D   128
#define H   8
#define DH  16
#define DF  512
#define NQ_MAX  20000
#define NKV_MAX 20000
#define E_MAX   640000

// ---------------- scratch (device globals; no allocations allowed) ----------
__device__ float g_q[NQ_MAX * D];
__device__ float g_k[NKV_MAX * D];
__device__ float g_v[NKV_MAX * D];
__device__ float g_sa[NQ_MAX * D];
__device__ float g_feat[NQ_MAX * D];
__device__ float g_ff[NQ_MAX * D];

__device__ __align__(128) __nv_bfloat16 g_qf_hi[NQ_MAX * D];
__device__ __align__(128) __nv_bfloat16 g_qf_lo[NQ_MAX * D];
__device__ __align__(128) __nv_bfloat16 g_kvf_hi[NKV_MAX * D];
__device__ __align__(128) __nv_bfloat16 g_kvf_lo[NKV_MAX * D];
__device__ __align__(128) __nv_bfloat16 g_attn_hi[NQ_MAX * D];
__device__ __align__(128) __nv_bfloat16 g_attn_lo[NQ_MAX * D];
__device__ __align__(128) __nv_bfloat16 g_feat_hi[NQ_MAX * D];
__device__ __align__(128) __nv_bfloat16 g_feat_lo[NQ_MAX * D];
__device__ __align__(128) __nv_bfloat16 g_hid_hi[NQ_MAX * DF];
__device__ __align__(128) __nv_bfloat16 g_hid_lo[NQ_MAX * DF];
__device__ __align__(128) __nv_bfloat16 g_Wq_hi[D * D],  g_Wq_lo[D * D];
__device__ __align__(128) __nv_bfloat16 g_Wk_hi[D * D],  g_Wk_lo[D * D];
__device__ __align__(128) __nv_bfloat16 g_Wv_hi[D * D],  g_Wv_lo[D * D];
__device__ __align__(128) __nv_bfloat16 g_Wo_hi[D * D],  g_Wo_lo[D * D];
__device__ __align__(128) __nv_bfloat16 g_W1_hi[DF * D], g_W1_lo[DF * D];
__device__ __align__(128) __nv_bfloat16 g_W2_hi[D * DF], g_W2_lo[D * DF];

// CSR scratch
__device__ int g_cnt[NQ_MAX];
__device__ int g_off[NQ_MAX + 1];
__device__ int g_cursor[NQ_MAX];
__device__ int g_slist[E_MAX];

// ---------------- helpers ------------------------------------------------------
__device__ __forceinline__ uint32_t smem_u32(const void* p) {
    uint32_t a;
    asm("{ .reg .u64 t; cvta.to.shared.u64 t, %1; cvt.u32.u64 %0, t; }" : "=r"(a) : "l"(p));
    return a;
}
__device__ __forceinline__ void f32_hilo(float x, __nv_bfloat16& h, __nv_bfloat16& l) {
    h = __float2bfloat16(x);
    l = __float2bfloat16(x - __bfloat162float(h));
}
__device__ __forceinline__ void mma16816(float* c, const uint32_t* a, const uint32_t* b) {
    asm volatile(
        "mma.sync.aligned.m16n8k16.row.col.f32.bf16.bf16.f32 "
        "{%0,%1,%2,%3}, {%4,%5,%6,%7}, {%8,%9}, {%0,%1,%2,%3};"
        : "+f"(c[0]), "+f"(c[1]), "+f"(c[2]), "+f"(c[3])
        : "r"(a[0]), "r"(a[1]), "r"(a[2]), "r"(a[3]), "r"(b[0]), "r"(b[1]));
}

// ---------------- conversions -------------------------------------------------
__global__ void conv_inputs(const float* __restrict__ qf, const float* __restrict__ kvf,
                            int nq, int ntot) {
    int i = blockIdx.x * blockDim.x + threadIdx.x;
    if (i >= ntot) return;
    __nv_bfloat16 h, l;
    if (i < nq) {
        f32_hilo(qf[i], h, l);
        g_qf_hi[i] = h; g_qf_lo[i] = l;
    } else {
        int j = i - nq;
        f32_hilo(kvf[j], h, l);
        g_kvf_hi[j] = h; g_kvf_lo[j] = l;
    }
}

__global__ void conv_weights(const float* __restrict__ Wq, const float* __restrict__ Wk,
                             const float* __restrict__ Wv, const float* __restrict__ Wo,
                             const float* __restrict__ W1, const float* __restrict__ W2) {
    int i = blockIdx.x * blockDim.x + threadIdx.x;     // 0 .. 196607
    const float* src; __nv_bfloat16 *ho, *lo_; int r;
    if (i < 65536) {
        int which = i >> 14; r = i & 16383;
        if (which == 0)      { src = Wq; ho = g_Wq_hi; lo_ = g_Wq_lo; }
        else if (which == 1) { src = Wk; ho = g_Wk_hi; lo_ = g_Wk_lo; }
        else if (which == 2) { src = Wv; ho = g_Wv_hi; lo_ = g_Wv_lo; }
        else                 { src = Wo; ho = g_Wo_hi; lo_ = g_Wo_lo; }
    } else if (i < 131072) { r = i - 65536;  src = W1; ho = g_W1_hi; lo_ = g_W1_lo; }
    else                   { r = i - 131072; src = W2; ho = g_W2_hi; lo_ = g_W2_lo; }
    __nv_bfloat16 h, l;
    f32_hilo(src[r], h, l);
    ho[r] = h; lo_[r] = l;
}

// ---------------- tensor-core GEMM body: out[N][C] = X[N][K] @ W[C][K]^T -----
#define KSTB  80
#define BUF   (128 * KSTB)                 // 10240 bytes
#define STAGE (4 * BUF)                    // 40960 per stage
#define GEMM_SMEM (2 * STAGE)              // 81920 bytes

__device__ __forceinline__ void stage32(uint32_t sbase, int tid,
    const __nv_bfloat16* __restrict__ Ahi, const __nv_bfloat16* __restrict__ Alo,
    const __nv_bfloat16* __restrict__ Bhi, const __nv_bfloat16* __restrict__ Blo,
    int row0, int c0, int kc, int K, int Nrows) {
#pragma unroll
    for (int j = 0; j < 8; j++) {
        int id  = tid + (j << 8);
        int buf = id >> 9;
        int rem = id & 511;
        int r   = rem >> 2;
        int c16 = rem & 3;
        const __nv_bfloat16* g;
        int rg;
        if (buf == 0)      { g = Ahi; rg = min(row0 + r, Nrows - 1); }
        else if (buf == 1) { g = Alo; rg = min(row0 + r, Nrows - 1); }
        else if (buf == 2) { g = Bhi; rg = c0 + r; }
        else               { g = Blo; rg = c0 + r; }
        uint32_t daddr = sbase + buf * BUF + r * KSTB + c16 * 16;
        unsigned long long gsrc =
            (unsigned long long)__cvta_generic_to_global(g + (size_t)rg * K + kc + c16 * 8);
        asm volatile("cp.async.cg.shared.global [%0], [%1], 16;"
                     :: "r"(daddr), "l"(gsrc) : "memory");
    }
}

template<bool BIAS, bool RELU, bool WF32, bool WHILO>
__device__ __forceinline__ void gemm_body(
    char* smem,
    const __nv_bfloat16* __restrict__ Ahi, const __nv_bfloat16* __restrict__ Alo,
    const __nv_bfloat16* __restrict__ Bhi, const __nv_bfloat16* __restrict__ Blo,
    const float* __restrict__ bias,
    float* __restrict__ outf, __nv_bfloat16* __restrict__ outhi,
    __nv_bfloat16* __restrict__ outlo, int Nrows, int C, int K, int row0, int c0) {
    const uint32_t sb = smem_u32(smem);
    const int tid  = threadIdx.x;
    const int wid  = tid >> 5;
    const int lane = tid & 31;
    const int wr   = wid >> 2;
    const int wc   = wid & 3;
    const int gq   = lane >> 2;
    const int tg   = lane & 3;

    float acc[4][4][4];
#pragma unroll
    for (int mi = 0; mi < 4; mi++)
#pragma unroll
        for (int ni = 0; ni < 4; ni++)
#pragma unroll
            for (int t = 0; t < 4; t++) acc[mi][ni][t] = 0.f;

    const int NC = K >> 5;
    stage32(sb, tid, Ahi, Alo, Bhi, Blo, row0, c0, 0, K, Nrows);
    asm volatile("cp.async.commit_group;" ::: "memory");

    for (int ch = 0; ch < NC; ch++) {
        if (ch + 1 < NC) {
            stage32(sb + ((ch + 1) & 1) * STAGE, tid, Ahi, Alo, Bhi, Blo,
                    row0, c0, (ch + 1) << 5, K, Nrows);
            asm volatile("cp.async.commit_group;" ::: "memory");
            asm volatile("cp.async.wait_group 1;" ::: "memory");
        } else {
            asm volatile("cp.async.wait_group 0;" ::: "memory");
        }
        __syncthreads();

        const char* sAh = smem + (ch & 1) * STAGE;
        const char* sAl = sAh + BUF;
        const char* sBh = sAh + 2 * BUF;
        const char* sBl = sAh + 3 * BUF;

#pragma unroll
        for (int ks = 0; ks < 2; ks++) {
            const int kbyte = (ks << 5) + (tg << 2);
            uint32_t bh[4][2], bl[4][2];
#pragma unroll
            for (int ni = 0; ni < 4; ni++) {
                int n = wc * 32 + ni * 8 + gq;
                const char* pbh = sBh + n * KSTB + kbyte;
                const char* pbl = sBl + n * KSTB + kbyte;
                bh[ni][0] = *(const uint32_t*)(pbh);
                bh[ni][1] = *(const uint32_t*)(pbh + 16);
                bl[ni][0] = *(const uint32_t*)(pbl);
                bl[ni][1] = *(const uint32_t*)(pbl + 16);
            }
#pragma unroll
            for (int mi = 0; mi < 4; mi++) {
                int r = wr * 64 + mi * 16 + gq;
                const char* pah = sAh + r * KSTB + kbyte;
                const char* pal = sAl + r * KSTB + kbyte;
                uint32_t ah[4], al[4];
                ah[0] = *(const uint32_t*)(pah);
                ah[1] = *(const uint32_t*)(pah + 8 * KSTB);
                ah[2] = *(const uint32_t*)(pah + 16);
                ah[3] = *(const uint32_t*)(pah + 8 * KSTB + 16);
                al[0] = *(const uint32_t*)(pal);
                al[1] = *(const uint32_t*)(pal + 8 * KSTB);
                al[2] = *(const uint32_t*)(pal + 16);
                al[3] = *(const uint32_t*)(pal + 8 * KSTB + 16);
#pragma unroll
                for (int ni = 0; ni < 4; ni++) {
                    mma16816(acc[mi][ni], ah, bh[ni]);
                    mma16816(acc[mi][ni], ah, bl[ni]);
                    mma16816(acc[mi][ni], al, bh[ni]);
                }
            }
        }
        __syncthreads();
    }

    // epilogue: registers -> gmem
#pragma unroll
    for (int mi = 0; mi < 4; mi++) {
#pragma unroll
        for (int half = 0; half < 2; half++) {
            int r = row0 + wr * 64 + mi * 16 + gq + half * 8;
            if (r >= Nrows) continue;
#pragma unroll
            for (int ni = 0; ni < 4; ni++) {
                int c = c0 + wc * 32 + ni * 8 + tg * 2;
                float v0 = acc[mi][ni][half * 2 + 0];
                float v1 = acc[mi][ni][half * 2 + 1];
                if (BIAS) { v0 += bias[c]; v1 += bias[c + 1]; }
                if (RELU) { v0 = fmaxf(v0, 0.f); v1 = fmaxf(v1, 0.f); }
                size_t o = (size_t)r * C + c;
                if (WF32) *(float2*)(outf + o) = make_float2(v0, v1);
                if (WHILO) {
                    __nv_bfloat16 h0, l0, h1, l1;
                    f32_hilo(v0, h0, l0); f32_hilo(v1, h1, l1);
                    __nv_bfloat162 hh; hh.x = h0; hh.y = h1;
                    __nv_bfloat162 ll; ll.x = l0; ll.y = l1;
                    *(__nv_bfloat162*)(outhi + o) = hh;
                    *(__nv_bfloat162*)(outlo + o) = ll;
                }
            }
        }
    }
}

template<bool BIAS, bool RELU, bool WF32, bool WHILO>
__global__ void __launch_bounds__(256, 2)
gemm_mma(const __nv_bfloat16* __restrict__ Ahi, const __nv_bfloat16* __restrict__ Alo,
         const __nv_bfloat16* __restrict__ Bhi, const __nv_bfloat16* __restrict__ Blo,
         const float* __restrict__ bias,
         float* __restrict__ outf, __nv_bfloat16* __restrict__ outhi,
         __nv_bfloat16* __restrict__ outlo, int Nrows, int C, int K) {
    extern __shared__ char smem[];
    gemm_body<BIAS, RELU, WF32, WHILO>(smem, Ahi, Alo, Bhi, Blo, bias,
                                       outf, outhi, outlo, Nrows, C, K,
                                       blockIdx.x * 128, blockIdx.y * 128);
}

// fused q/k/v projections: blockIdx.y selects which GEMM; operands are globals
__global__ void __launch_bounds__(256, 2)
proj_qkv(int NQ, int NKV) {
    extern __shared__ char smem[];
    const int row0 = blockIdx.x * 128;
    if (blockIdx.y == 0) {
        if (row0 >= NQ) return;
        gemm_body<false, false, true, false>(smem, g_qf_hi, g_qf_lo, g_Wq_hi, g_Wq_lo,
                                             nullptr, g_q, nullptr, nullptr, NQ, D, D, row0, 0);
    } else if (blockIdx.y == 1) {
        if (row0 >= NKV) return;
        gemm_body<false, false, true, false>(smem, g_kvf_hi, g_kvf_lo, g_Wk_hi, g_Wk_lo,
                                             nullptr, g_k, nullptr, nullptr, NKV, D, D, row0, 0);
    } else {
        if (row0 >= NKV) return;
        gemm_body<false, false, true, false>(smem, g_kvf_hi, g_kvf_lo, g_Wv_hi, g_Wv_lo,
                                             nullptr, g_v, nullptr, nullptr, NKV, D, D, row0, 0);
    }
}

// ---------------- CSR build --------------------------------------------------
__global__ void hist_kernel(const int* __restrict__ dst, int* __restrict__ cnt, int E) {
    int e = blockIdx.x * blockDim.x + threadIdx.x;
    if (e < E) atomicAdd(&cnt[dst[e]], 1);
}

// single-block scan, smem-staged for coalescing:
// coalesced gmem->smem, per-thread serial chunk prefix in smem, coalesced store.
__global__ __launch_bounds__(1024)
void scan_kernel(const int* __restrict__ cnt, int* __restrict__ off,
                 int* __restrict__ cursor, int n) {
    extern __shared__ int sc[];
    __shared__ int wsum[32];
    const int tid  = threadIdx.x;
    const int lane = tid & 31;
    const int wid  = tid >> 5;

    for (int i = tid; i < n; i += 1024) sc[i] = cnt[i];
    __syncthreads();

    const int chunk = (n + 1023) >> 10;
    const int s = min(tid * chunk, n);
    const int e = min(s + chunk, n);

    int sum = 0;
    for (int i = s; i < e; i++) sum += sc[i];

    int x = sum;
#pragma unroll
    for (int o = 1; o < 32; o <<= 1) {
        int y = __shfl_up_sync(0xffffffffu, x, o);
        if (lane >= o) x += y;
    }
    if (lane == 31) wsum[wid] = x;
    __syncthreads();
    if (tid < 32) {
        int w = wsum[tid];
#pragma unroll
        for (int o = 1; o < 32; o <<= 1) {
            int y = __shfl_up_sync(0xffffffffu, w, o);
            if (tid >= o) w += y;
        }
        wsum[tid] = w;
    }
    __syncthreads();

    int run = x - sum + (wid > 0 ? wsum[wid - 1] : 0);   // exclusive prefix
    for (int i = s; i < e; i++) {
        int c = sc[i];
        sc[i] = run;
        run += c;
    }
    __syncthreads();

    for (int i = tid; i < n; i += 1024) {
        int v = sc[i];
        off[i] = v;
        cursor[i] = v;
    }
    if (tid == 1023) off[n] = run;    // last thread's run == grand total
}

__global__ void fill_kernel(const int* __restrict__ dst, const int* __restrict__ src,
                            int* __restrict__ cursor, int* __restrict__ slist, int E) {
    int e = blockIdx.x * blockDim.x + threadIdx.x;
    if (e < E) {
        int p = atomicAdd(&cursor[dst[e]], 1);
        slist[p] = src[e];
    }
}

// ---------------- fused edge-softmax attention (one warp per dst node) -------
__global__ __launch_bounds__(256)
void attn_gather(const float* __restrict__ k, const float* __restrict__ q,
                 const float* __restrict__ v, const int* __restrict__ slist,
                 const int* __restrict__ off,
                 __nv_bfloat16* __restrict__ out_hi, __nv_bfloat16* __restrict__ out_lo,
                 int NQ) {
    int warp = (blockIdx.x * blockDim.x + threadIdx.x) >> 5;
    int lane = threadIdx.x & 31;
    if (warp >= NQ) return;
    const int d = warp;

    float4 qv = *(const float4*)(q + (size_t)d * D + lane * 4);
    int i0 = off[d], i1 = off[d + 1];

    float mA = -1e30f, sA = 0.f, mB = -1e30f, sB = 0.f;
    float4 aA = make_float4(0.f, 0.f, 0.f, 0.f);
    float4 aB = make_float4(0.f, 0.f, 0.f, 0.f);

    int i = i0;
    for (; i + 1 < i1; i += 2) {
        int s0 = slist[i], s1 = slist[i + 1];
        float4 k0 = *(const float4*)(k + (size_t)s0 * D + lane * 4);
        float4 k1 = *(const float4*)(k + (size_t)s1 * D + lane * 4);
        float4 v0 = *(const float4*)(v + (size_t)s0 * D + lane * 4);
        float4 v1 = *(const float4*)(v + (size_t)s1 * D + lane * 4);
        float d0 = k0.x * qv.x + k0.y * qv.y + k0.z * qv.z + k0.w * qv.w;
        float d1 = k1.x * qv.x + k1.y * qv.y + k1.z * qv.z + k1.w * qv.w;
        d0 += __shfl_xor_sync(0xffffffffu, d0, 1);
        d1 += __shfl_xor_sync(0xffffffffu, d1, 1);
        d0 += __shfl_xor_sync(0xffffffffu, d0, 2);
        d1 += __shfl_xor_sync(0xffffffffu, d1, 2);
        float x0 = d0 * 0.25f, x1 = d1 * 0.25f;
        float mn0 = fmaxf(mA, x0);
        float mn1 = fmaxf(mB, x1);
        float c0 = __expf(mA - mn0), p0 = __expf(x0 - mn0);
        float c1 = __expf(mB - mn1), p1 = __expf(x1 - mn1);
        sA = sA * c0 + p0;
        sB = sB * c1 + p1;
        aA.x = aA.x * c0 + p0 * v0.x;  aB.x = aB.x * c1 + p1 * v1.x;
        aA.y = aA.y * c0 + p0 * v0.y;  aB.y = aB.y * c1 + p1 * v1.y;
        aA.z = aA.z * c0 + p0 * v0.z;  aB.z = aB.z * c1 + p1 * v1.z;
        aA.w = aA.w * c0 + p0 * v0.w;  aB.w = aB.w * c1 + p1 * v1.w;
        mA = mn0; mB = mn1;
    }
    if (i < i1) {
        int s0 = slist[i];
        float4 k0 = *(const float4*)(k + (size_t)s0 * D + lane * 4);
        float4 v0 = *(const float4*)(v + (size_t)s0 * D + lane * 4);
        float d0 = k0.x * qv.x + k0.y * qv.y + k0.z * qv.z + k0.w * qv.w;
        d0 += __shfl_xor_sync(0xffffffffu, d0, 1);
        d0 += __shfl_xor_sync(0xffffffffu, d0, 2);
        float x0 = d0 * 0.25f;
        float mn0 = fmaxf(mA, x0);
        float c0 = __expf(mA - mn0), p0 = __expf(x0 - mn0);
        sA = sA * c0 + p0;
        aA.x = aA.x * c0 + p0 * v0.x;
        aA.y = aA.y * c0 + p0 * v0.y;
        aA.z = aA.z * c0 + p0 * v0.z;
        aA.w = aA.w * c0 + p0 * v0.w;
        mA = mn0;
    }
    float mn = fmaxf(mA, mB);
    float cA = __expf(mA - mn), cB = __expf(mB - mn);
    float sden = sA * cA + sB * cB;
    float4 acc;
    acc.x = aA.x * cA + aB.x * cB;
    acc.y = aA.y * cA + aB.y * cB;
    acc.z = aA.z * cA + aB.z * cB;
    acc.w = aA.w * cA + aB.w * cB;

    float inv = (sden > 0.f) ? (1.f / sden) : 0.f;
    float4 o = make_float4(acc.x * inv, acc.y * inv, acc.z * inv, acc.w * inv);
    __nv_bfloat16 h[4], l[4];
    f32_hilo(o.x, h[0], l[0]); f32_hilo(o.y, h[1], l[1]);
    f32_hilo(o.z, h[2], l[2]); f32_hilo(o.w, h[3], l[3]);
    size_t ob = (size_t)d * D + lane * 4;
    *(uint2*)(out_hi + ob) = *(uint2*)h;
    *(uint2*)(out_lo + ob) = *(uint2*)l;
}

// ---------------- residual add + layernorm ------------------------------------
template<bool WHILO>
__global__ void add_ln_kernel(const float* __restrict__ a, const float* __restrict__ b,
                              const float* __restrict__ gamma, const float* __restrict__ beta,
                              float* __restrict__ out,
                              __nv_bfloat16* __restrict__ out_hi,
                              __nv_bfloat16* __restrict__ out_lo) {
    int row = blockIdx.x;
    int t   = threadIdx.x;
    float x = a[(size_t)row * D + t] + b[(size_t)row * D + t];
    float s = x, s2 = x * x;
#pragma unroll
    for (int off = 16; off; off >>= 1) {
        s  += __shfl_xor_sync(0xffffffffu, s,  off);
        s2 += __shfl_xor_sync(0xffffffffu, s2, off);
    }
    __shared__ float ps[4], ps2[4];
    if ((t & 31) == 0) { ps[t >> 5] = s; ps2[t >> 5] = s2; }
    __syncthreads();
    s  = ps[0]  + ps[1]  + ps[2]  + ps[3];
    s2 = ps2[0] + ps2[1] + ps2[2] + ps2[3];
    float mu  = s * (1.f / 128.f);
    float var = s2 * (1.f / 128.f) - mu * mu;
    float invs = rsqrtf(var + 1e-5f);
    float y = (x - mu) * invs * gamma[t] + beta[t];
    out[(size_t)row * D + t] = y;
    if (WHILO) {
        __nv_bfloat16 h, l;
        f32_hilo(y, h, l);
        out_hi[(size_t)row * D + t] = h;
        out_lo[(size_t)row * D + t] = l;
    }
}

// ---------------- launch -----------------------------------------------------
extern "C" void kernel_launch(void* const* d_in, const int* in_sizes, int n_in,
                              void* d_out, int out_size) {
    const float* q_feat  = (const float*)d_in[0];
    const float* kv_feat = (const float*)d_in[1];
    const int*   src     = (const int*)d_in[2];
    const int*   dst     = (const int*)d_in[3];
    const float* Wq      = (const float*)d_in[4];
    const float* Wk      = (const float*)d_in[5];
    const float* Wv      = (const float*)d_in[6];
    const float* Wo      = (const float*)d_in[7];
    const float* W1      = (const float*)d_in[8];
    const float* bf1     = (const float*)d_in[9];
    const float* W2      = (const float*)d_in[10];
    const float* bf2     = (const float*)d_in[11];
    const float* ln1_g   = (const float*)d_in[12];
    const float* ln1_b   = (const float*)d_in[13];
    const float* ln2_g   = (const float*)d_in[14];
    const float* ln2_b   = (const float*)d_in[15];

    const int NQ  = in_sizes[0] / D;
    const int NKV = in_sizes[1] / D;
    const int E   = in_sizes[2];

    float *qp, *kp, *vp, *sap, *featp, *ffp;
    __nv_bfloat16 *ath, *atl, *fth, *ftl, *hdh, *hdl;
    __nv_bfloat16 *woh, *wol, *w1h, *w1l, *w2h, *w2l;
    int *cntp, *offp, *curp, *slistp;
    cudaGetSymbolAddress((void**)&qp,    g_q);
    cudaGetSymbolAddress((void**)&kp,    g_k);
    cudaGetSymbolAddress((void**)&vp,    g_v);
    cudaGetSymbolAddress((void**)&sap,   g_sa);
    cudaGetSymbolAddress((void**)&featp, g_feat);
    cudaGetSymbolAddress((void**)&ffp,   g_ff);
    cudaGetSymbolAddress((void**)&ath,   g_attn_hi); cudaGetSymbolAddress((void**)&atl, g_attn_lo);
    cudaGetSymbolAddress((void**)&fth,   g_feat_hi); cudaGetSymbolAddress((void**)&ftl, g_feat_lo);
    cudaGetSymbolAddress((void**)&hdh,   g_hid_hi);  cudaGetSymbolAddress((void**)&hdl, g_hid_lo);
    cudaGetSymbolAddress((void**)&woh,   g_Wo_hi);   cudaGetSymbolAddress((void**)&wol, g_Wo_lo);
    cudaGetSymbolAddress((void**)&w1h,   g_W1_hi);   cudaGetSymbolAddress((void**)&w1l, g_W1_lo);
    cudaGetSymbolAddress((void**)&w2h,   g_W2_hi);   cudaGetSymbolAddress((void**)&w2l, g_W2_lo);
    cudaGetSymbolAddress((void**)&cntp,  g_cnt);
    cudaGetSymbolAddress((void**)&offp,  g_off);
    cudaGetSymbolAddress((void**)&curp,  g_cursor);
    cudaGetSymbolAddress((void**)&slistp, g_slist);

    cudaFuncSetAttribute(proj_qkv,
                         cudaFuncAttributeMaxDynamicSharedMemorySize, GEMM_SMEM);
    cudaFuncSetAttribute(gemm_mma<false, false, true,  false>,
                         cudaFuncAttributeMaxDynamicSharedMemorySize, GEMM_SMEM);
    cudaFuncSetAttribute(gemm_mma<true,  true,  false, true>,
                         cudaFuncAttributeMaxDynamicSharedMemorySize, GEMM_SMEM);
    cudaFuncSetAttribute(gemm_mma<true,  false, true,  false>,
                         cudaFuncAttributeMaxDynamicSharedMemorySize, GEMM_SMEM);
    const int scan_smem = (NQ_MAX + 1) * sizeof(int);
    cudaFuncSetAttribute(scan_kernel,
                         cudaFuncAttributeMaxDynamicSharedMemorySize, scan_smem);

    const int MTq  = (NQ + 127) / 128;
    const int MTkv = (NKV + 127) / 128;
    const int MTmax = MTq > MTkv ? MTq : MTkv;
    int eb = (E + 255) / 256;

    // conversions (2 launches)
    int ntot = (NQ + NKV) * D;
    conv_inputs<<<(ntot + 255) / 256, 256>>>(q_feat, kv_feat, NQ * D, ntot);
    conv_weights<<<768, 256>>>(Wq, Wk, Wv, Wo, W1, W2);

    // CSR part 1 (independent of proj)
    cudaMemsetAsync(cntp, 0, (size_t)NQ * sizeof(int));
    hist_kernel<<<eb, 256>>>(dst, cntp, E);

    // fused q/k/v projections (placed at graph node idx 4 for ncu capture)
    proj_qkv<<<dim3(MTmax, 3), 256, GEMM_SMEM>>>(NQ, NKV);

    // CSR part 2
    scan_kernel<<<1, 1024, NQ * (int)sizeof(int)>>>(cntp, offp, curp, NQ);
    fill_kernel<<<eb, 256>>>(dst, src, curp, slistp, E);

    // fused one-pass edge-softmax attention (one warp per dst)
    int ablocks = (NQ * 32 + 255) / 256;
    attn_gather<<<ablocks, 256>>>(kp, qp, vp, slistp, offp, ath, atl, NQ);

    // output projection + residual LN
    gemm_mma<false, false, true, false><<<dim3(MTq, 1), 256, GEMM_SMEM>>>(
        ath, atl, woh, wol, nullptr, sap, nullptr, nullptr, NQ, D, D);
    add_ln_kernel<true><<<NQ, 128>>>(q_feat, sap, ln1_g, ln1_b, featp, fth, ftl);

    // FFN
    gemm_mma<true, true, false, true><<<dim3(MTq, 4), 256, GEMM_SMEM>>>(
        fth, ftl, w1h, w1l, bf1, nullptr, hdh, hdl, NQ, DF, D);
    gemm_mma<true, false, true, false><<<dim3(MTq, 1), 256, GEMM_SMEM>>>(
        hdh, hdl, w2h, w2l, bf2, ffp, nullptr, nullptr, NQ, D, DF);

    // final residual LN -> output
    add_ln_kernel<false><<<NQ, 128>>>(featp, ffp, ln2_g, ln2_b, (float*)d_out, nullptr, nullptr);
}